// round 3
// baseline (speedup 1.0000x reference)
#include <cuda_runtime.h>
#include <math.h>

// Problem constants
#define NE    1024      // n_embd
#define NH    16        // n_head
#define HS    64        // head_size
#define TT    2048      // seq len
#define BB    2         // batch
#define BT    (BB*TT)   // total rows = 4096
#define FF    4096      // 4*n_embd
#define LN_EPS 1e-5f

// -------- scratch (device globals; no allocation allowed) --------
__device__ float g_h[BT * NE];      // ln1 out, reused for ln2 out
__device__ float g_q[BT * NE];
__device__ float g_k[BT * NE];
__device__ float g_v[BT * NE];
__device__ float g_attn[BT * NE];
__device__ float g_ff[BT * FF];     // 64 MB

// ============================================================
// LayerNorm: one block per row (1024 elems), 256 threads
// ============================================================
__global__ __launch_bounds__(256) void ln_kernel(
    const float* __restrict__ X, const float* __restrict__ G,
    const float* __restrict__ Be, float* __restrict__ Y)
{
    const int row = blockIdx.x;
    const float* xr = X + (size_t)row * NE;
    const int tid = threadIdx.x;

    // each thread loads exactly one float4 (1024/4 = 256)
    float4 xv = ((const float4*)xr)[tid];
    float s  = xv.x + xv.y + xv.z + xv.w;
    float ss = xv.x*xv.x + xv.y*xv.y + xv.z*xv.z + xv.w*xv.w;

    // block reduction
    __shared__ float red_s[32], red_q[32];
    const int lane = tid & 31, wid = tid >> 5;
    #pragma unroll
    for (int o = 16; o > 0; o >>= 1) {
        s  += __shfl_xor_sync(0xffffffffu, s, o);
        ss += __shfl_xor_sync(0xffffffffu, ss, o);
    }
    if (lane == 0) { red_s[wid] = s; red_q[wid] = ss; }
    __syncthreads();
    if (wid == 0) {
        s  = (lane < 8) ? red_s[lane] : 0.f;
        ss = (lane < 8) ? red_q[lane] : 0.f;
        #pragma unroll
        for (int o = 4; o > 0; o >>= 1) {
            s  += __shfl_xor_sync(0xffffffffu, s, o);
            ss += __shfl_xor_sync(0xffffffffu, ss, o);
        }
        if (lane == 0) { red_s[0] = s; red_q[0] = ss; }
    }
    __syncthreads();
    const float mu   = red_s[0] * (1.0f / NE);
    const float var  = red_q[0] * (1.0f / NE) - mu * mu;
    const float rstd = rsqrtf(var + LN_EPS);

    float4 gv = ((const float4*)G)[tid];
    float4 bv = ((const float4*)Be)[tid];
    float4 yv;
    yv.x = (xv.x - mu) * rstd * gv.x + bv.x;
    yv.y = (xv.y - mu) * rstd * gv.y + bv.y;
    yv.z = (xv.z - mu) * rstd * gv.z + bv.z;
    yv.w = (xv.w - mu) * rstd * gv.w + bv.w;
    ((float4*)(Y + (size_t)row * NE))[tid] = yv;
}

// ============================================================
// Tiled SGEMM: C[M,N] = A[M,K] @ W[K,N] (+bias)(+relu)(+res)
// BM=128, BN=64, BK=16, 256 threads, 8x4 per thread
// ============================================================
template<bool BIAS, bool RELU, bool RES>
__global__ __launch_bounds__(256) void gemm_kernel(
    const float* __restrict__ A, const float* __restrict__ W,
    const float* __restrict__ bias, const float* __restrict__ res,
    float* __restrict__ C, int M, int N, int K)
{
    __shared__ float As[16][128];  // [k][m] (transposed)
    __shared__ float Ws[16][64];   // [k][n]

    const int tid = threadIdx.x;
    const int tx = tid & 15, ty = tid >> 4;      // 16 x 16
    const int n0 = blockIdx.x * 64;
    const int m0 = blockIdx.y * 128;

    // A tile: 128 rows x 4 float4 = 512 float4 -> 2 per thread
    const int a_idx0 = tid * 2;
    // W tile: 16 rows x 16 float4 = 256 float4 -> 1 per thread
    const int wrow = tid >> 4, wc4 = tid & 15;

    float acc[8][4];
    #pragma unroll
    for (int i = 0; i < 8; i++)
        #pragma unroll
        for (int j = 0; j < 4; j++) acc[i][j] = 0.f;

    for (int k0 = 0; k0 < K; k0 += 16) {
        #pragma unroll
        for (int u = 0; u < 2; u++) {
            const int idx = a_idx0 + u;
            const int arow = idx >> 2, ac4 = idx & 3;
            float4 av = *(const float4*)(A + (size_t)(m0 + arow) * K + k0 + ac4 * 4);
            As[ac4*4 + 0][arow] = av.x;
            As[ac4*4 + 1][arow] = av.y;
            As[ac4*4 + 2][arow] = av.z;
            As[ac4*4 + 3][arow] = av.w;
        }
        float4 wv = *(const float4*)(W + (size_t)(k0 + wrow) * N + n0 + wc4 * 4);
        *(float4*)&Ws[wrow][wc4 * 4] = wv;
        __syncthreads();

        #pragma unroll
        for (int kk = 0; kk < 16; kk++) {
            float a[8], w[4];
            #pragma unroll
            for (int i = 0; i < 8; i++) a[i] = As[kk][ty * 8 + i];
            #pragma unroll
            for (int j = 0; j < 4; j++) w[j] = Ws[kk][tx * 4 + j];
            #pragma unroll
            for (int i = 0; i < 8; i++)
                #pragma unroll
                for (int j = 0; j < 4; j++) acc[i][j] = fmaf(a[i], w[j], acc[i][j]);
        }
        __syncthreads();
    }

    // epilogue (float4 stores)
    float4 bv = make_float4(0.f, 0.f, 0.f, 0.f);
    if (BIAS) bv = *(const float4*)(bias + n0 + tx * 4);
    #pragma unroll
    for (int i = 0; i < 8; i++) {
        const size_t off = (size_t)(m0 + ty * 8 + i) * N + n0 + tx * 4;
        float4 v = make_float4(acc[i][0], acc[i][1], acc[i][2], acc[i][3]);
        if (BIAS) { v.x += bv.x; v.y += bv.y; v.z += bv.z; v.w += bv.w; }
        if (RELU) {
            v.x = fmaxf(v.x, 0.f); v.y = fmaxf(v.y, 0.f);
            v.z = fmaxf(v.z, 0.f); v.w = fmaxf(v.w, 0.f);
        }
        if (RES) {
            float4 r = *(const float4*)(res + off);
            v.x += r.x; v.y += r.y; v.z += r.z; v.w += r.w;
        }
        *(float4*)(C + off) = v;
    }
}

// ============================================================
// Causal flash attention, fp32.
// grid = (T/64, B*H), block = 64 threads (1 query per thread)
// Q/K/V layout: [B, T, H*HS] with col = h*64+d; scale folded into Q.
// ============================================================
__global__ __launch_bounds__(64) void attn_kernel(
    const float* __restrict__ Q, const float* __restrict__ K,
    const float* __restrict__ V, float* __restrict__ O)
{
    const int bh = blockIdx.y;
    const int b = bh >> 4, h = bh & 15;
    const int m0 = blockIdx.x * 64;
    const int tid = threadIdx.x;
    const size_t base = (size_t)b * TT * NE + h * HS;

    __shared__ float qs[64][65];   // padded: per-thread row reads conflict-free
    __shared__ float ks[64][64];
    __shared__ float vs[64][64];

    // load Q tile (64 rows x 16 float4)
    for (int i = tid; i < 64 * 16; i += 64) {
        const int r = i >> 4, c4 = i & 15;
        float4 t = *(const float4*)(Q + base + (size_t)(m0 + r) * NE + c4 * 4);
        qs[r][c4*4+0] = t.x; qs[r][c4*4+1] = t.y;
        qs[r][c4*4+2] = t.z; qs[r][c4*4+3] = t.w;
    }
    __syncthreads();

    float qreg[HS], o[HS];
    const float scale = 0.03125f;   // 1024^-0.5 (faithful to source: full C)
    #pragma unroll
    for (int d = 0; d < HS; d++) { qreg[d] = qs[tid][d] * scale; o[d] = 0.f; }
    float mi = -1e30f, li = 0.f;
    const int mq = m0 + tid;
    const int ntiles = blockIdx.x + 1;   // causal tile skipping

    for (int t = 0; t < ntiles; t++) {
        const int k0 = t * 64;
        __syncthreads();
        for (int i = tid; i < 64 * 16; i += 64) {
            const int r = i >> 4, c4 = i & 15;
            *(float4*)&ks[r][c4*4] = *(const float4*)(K + base + (size_t)(k0 + r) * NE + c4 * 4);
            *(float4*)&vs[r][c4*4] = *(const float4*)(V + base + (size_t)(k0 + r) * NE + c4 * 4);
        }
        __syncthreads();

        #pragma unroll 1
        for (int c = 0; c < 64; c += 16) {
            float s[16];
            #pragma unroll
            for (int j = 0; j < 16; j++) {
                float acc = 0.f;
                #pragma unroll
                for (int d = 0; d < HS; d++) acc = fmaf(qreg[d], ks[c + j][d], acc);
                s[j] = (k0 + c + j <= mq) ? acc : -1e30f;
            }
            float mnew = mi;
            #pragma unroll
            for (int j = 0; j < 16; j++) mnew = fmaxf(mnew, s[j]);
            const float corr = __expf(mi - mnew);
            li *= corr;
            #pragma unroll
            for (int d = 0; d < HS; d++) o[d] *= corr;
            #pragma unroll
            for (int j = 0; j < 16; j++) { s[j] = __expf(s[j] - mnew); li += s[j]; }
            #pragma unroll
            for (int j = 0; j < 16; j++)
                #pragma unroll
                for (int d = 0; d < HS; d++) o[d] = fmaf(s[j], vs[c + j][d], o[d]);
            mi = mnew;
        }
    }

    // normalize + coalesced store via smem stage
    const float inv = 1.0f / li;
    __syncthreads();
    #pragma unroll
    for (int d = 0; d < HS; d++) qs[tid][d] = o[d] * inv;
    __syncthreads();
    for (int i = tid; i < 64 * 16; i += 64) {
        const int r = i >> 4, c4 = i & 15;
        float4 t = make_float4(qs[r][c4*4], qs[r][c4*4+1], qs[r][c4*4+2], qs[r][c4*4+3]);
        *(float4*)(O + base + (size_t)(m0 + r) * NE + c4 * 4) = t;
    }
}

// ============================================================
// launch
// ============================================================
extern "C" void kernel_launch(void* const* d_in, const int* in_sizes, int n_in,
                              void* d_out, int out_size)
{
    const float* x  = (const float*)d_in[0];
    const float* Wq = (const float*)d_in[1];
    const float* Wk = (const float*)d_in[2];
    const float* Wv = (const float*)d_in[3];
    const float* Wo = (const float*)d_in[4];
    const float* bo = (const float*)d_in[5];
    const float* W1 = (const float*)d_in[6];
    const float* b1 = (const float*)d_in[7];
    const float* W2 = (const float*)d_in[8];
    const float* b2 = (const float*)d_in[9];
    const float* g1  = (const float*)d_in[10];
    const float* be1 = (const float*)d_in[11];
    const float* g2  = (const float*)d_in[12];
    const float* be2 = (const float*)d_in[13];
    float* out = (float*)d_out;

    float *h, *q, *k, *v, *attn, *ff;
    cudaGetSymbolAddress((void**)&h,    g_h);
    cudaGetSymbolAddress((void**)&q,    g_q);
    cudaGetSymbolAddress((void**)&k,    g_k);
    cudaGetSymbolAddress((void**)&v,    g_v);
    cudaGetSymbolAddress((void**)&attn, g_attn);
    cudaGetSymbolAddress((void**)&ff,   g_ff);

    // 1) h = ln1(x)
    ln_kernel<<<BT, 256>>>(x, g1, be1, h);

    // 2) q,k,v = h @ W{q,k,v}
    dim3 gQKV(NE / 64, BT / 128);
    gemm_kernel<false,false,false><<<gQKV, 256>>>(h, Wq, nullptr, nullptr, q, BT, NE, NE);
    gemm_kernel<false,false,false><<<gQKV, 256>>>(h, Wk, nullptr, nullptr, k, BT, NE, NE);
    gemm_kernel<false,false,false><<<gQKV, 256>>>(h, Wv, nullptr, nullptr, v, BT, NE, NE);

    // 3) causal flash attention
    dim3 gAtt(TT / 64, BB * NH);
    attn_kernel<<<gAtt, 64>>>(q, k, v, attn);

    // 4) out = attn @ Wo + bo + x   (x1 lives in d_out)
    gemm_kernel<true,false,true><<<gQKV, 256>>>(attn, Wo, bo, x, out, BT, NE, NE);

    // 5) h = ln2(out)
    ln_kernel<<<BT, 256>>>(out, g2, be2, h);

    // 6) ff = relu(h @ W1 + b1)
    dim3 gF1(FF / 64, BT / 128);
    gemm_kernel<true,true,false><<<gF1, 256>>>(h, W1, b1, nullptr, ff, BT, FF, NE);

    // 7) out = ff @ W2 + b2 + out
    dim3 gF2(NE / 64, BT / 128);
    gemm_kernel<true,false,true><<<gF2, 256>>>(ff, W2, b2, out, out, BT, NE, FF);
}

// round 7
// speedup vs baseline: 2.9784x; 2.9784x over previous
#include <cuda_runtime.h>
#include <cuda_bf16.h>
#include <cstdint>
#include <math.h>

// Problem constants
#define NE    1024
#define NH    16
#define HS    64
#define TT    2048
#define BB    2
#define BT    (BB*TT)   // 4096
#define FF    4096
#define LN_EPS 1e-5f

// ---------------- scratch (device globals) ----------------
__device__ __nv_bfloat16 g_h_hi[(size_t)BT*NE], g_h_lo[(size_t)BT*NE];
__device__ float g_q[(size_t)BT*NE], g_k[(size_t)BT*NE], g_v[(size_t)BT*NE];
__device__ __nv_bfloat16 g_at_hi[(size_t)BT*NE], g_at_lo[(size_t)BT*NE];
__device__ __nv_bfloat16 g_ff_hi[(size_t)BT*FF], g_ff_lo[(size_t)BT*FF];
// transposed+split weights: [N,K] K-major
__device__ __nv_bfloat16 g_wq_hi[NE*NE], g_wq_lo[NE*NE];
__device__ __nv_bfloat16 g_wk_hi[NE*NE], g_wk_lo[NE*NE];
__device__ __nv_bfloat16 g_wv_hi[NE*NE], g_wv_lo[NE*NE];
__device__ __nv_bfloat16 g_wo_hi[NE*NE], g_wo_lo[NE*NE];
__device__ __nv_bfloat16 g_w1_hi[(size_t)NE*FF], g_w1_lo[(size_t)NE*FF];
__device__ __nv_bfloat16 g_w2_hi[(size_t)NE*FF], g_w2_lo[(size_t)NE*FF];

// ---------------- PTX helpers ----------------
__device__ __forceinline__ uint32_t smem_u32(const void* p) {
    uint32_t a;
    asm("{ .reg .u64 t; cvta.to.shared.u64 t, %1; cvt.u32.u64 %0, t; }" : "=r"(a) : "l"(p));
    return a;
}

__device__ __forceinline__ void ldsm4(uint32_t* r, uint32_t addr) {
    asm volatile("ldmatrix.sync.aligned.m8n8.x4.shared.b16 {%0,%1,%2,%3}, [%4];"
        : "=r"(r[0]), "=r"(r[1]), "=r"(r[2]), "=r"(r[3]) : "r"(addr));
}

__device__ __forceinline__ void mma16816(float* c, const uint32_t* a, const uint32_t* b) {
    asm volatile("mma.sync.aligned.m16n8k16.row.col.f32.bf16.bf16.f32 "
        "{%0,%1,%2,%3}, {%4,%5,%6,%7}, {%8,%9}, {%0,%1,%2,%3};"
        : "+f"(c[0]), "+f"(c[1]), "+f"(c[2]), "+f"(c[3])
        : "r"(a[0]), "r"(a[1]), "r"(a[2]), "r"(a[3]), "r"(b[0]), "r"(b[1]));
}

// ---------------- weight transpose + bf16 split ----------------
// W[K,N] fp32 -> Thi/Tlo [N,K] bf16
__global__ __launch_bounds__(256) void wsplit_kernel(
    const float* __restrict__ W, __nv_bfloat16* __restrict__ Thi,
    __nv_bfloat16* __restrict__ Tlo, int K, int N)
{
    __shared__ float t[32][33];
    const int tx = threadIdx.x & 31, ty = threadIdx.x >> 5;   // 32 x 8
    const int nb = blockIdx.x * 32, kb = blockIdx.y * 32;
    #pragma unroll
    for (int i = 0; i < 4; i++) {
        const int k = kb + ty + i * 8;
        t[ty + i * 8][tx] = W[(size_t)k * N + nb + tx];
    }
    __syncthreads();
    #pragma unroll
    for (int i = 0; i < 4; i++) {
        const int n = nb + ty + i * 8;
        const float v = t[tx][ty + i * 8];
        const __nv_bfloat16 h = __float2bfloat16(v);
        Thi[(size_t)n * K + kb + tx] = h;
        Tlo[(size_t)n * K + kb + tx] = __float2bfloat16(v - __bfloat162float(h));
    }
}

// ---------------- LayerNorm -> bf16 hi/lo ----------------
__global__ __launch_bounds__(256) void ln_kernel(
    const float* __restrict__ X, const float* __restrict__ G,
    const float* __restrict__ Be, __nv_bfloat16* __restrict__ Yhi,
    __nv_bfloat16* __restrict__ Ylo)
{
    const int row = blockIdx.x;
    const float* xr = X + (size_t)row * NE;
    const int tid = threadIdx.x;

    float4 xv = ((const float4*)xr)[tid];
    float s  = xv.x + xv.y + xv.z + xv.w;
    float ss = xv.x*xv.x + xv.y*xv.y + xv.z*xv.z + xv.w*xv.w;

    __shared__ float red_s[32], red_q[32];
    const int lane = tid & 31, wid = tid >> 5;
    #pragma unroll
    for (int o = 16; o > 0; o >>= 1) {
        s  += __shfl_xor_sync(0xffffffffu, s, o);
        ss += __shfl_xor_sync(0xffffffffu, ss, o);
    }
    if (lane == 0) { red_s[wid] = s; red_q[wid] = ss; }
    __syncthreads();
    if (wid == 0) {
        s  = (lane < 8) ? red_s[lane] : 0.f;
        ss = (lane < 8) ? red_q[lane] : 0.f;
        #pragma unroll
        for (int o = 4; o > 0; o >>= 1) {
            s  += __shfl_xor_sync(0xffffffffu, s, o);
            ss += __shfl_xor_sync(0xffffffffu, ss, o);
        }
        if (lane == 0) { red_s[0] = s; red_q[0] = ss; }
    }
    __syncthreads();
    const float mu   = red_s[0] * (1.0f / NE);
    const float var  = red_q[0] * (1.0f / NE) - mu * mu;
    const float rstd = rsqrtf(var + LN_EPS);

    float4 gv = ((const float4*)G)[tid];
    float4 bv = ((const float4*)Be)[tid];
    float y0 = (xv.x - mu) * rstd * gv.x + bv.x;
    float y1 = (xv.y - mu) * rstd * gv.y + bv.y;
    float y2 = (xv.z - mu) * rstd * gv.z + bv.z;
    float y3 = (xv.w - mu) * rstd * gv.w + bv.w;

    __nv_bfloat16 h0 = __float2bfloat16(y0), h1 = __float2bfloat16(y1);
    __nv_bfloat16 h2 = __float2bfloat16(y2), h3 = __float2bfloat16(y3);
    __nv_bfloat162* hp = (__nv_bfloat162*)(Yhi + (size_t)row * NE + tid * 4);
    __nv_bfloat162* lp = (__nv_bfloat162*)(Ylo + (size_t)row * NE + tid * 4);
    hp[0] = __halves2bfloat162(h0, h1);
    hp[1] = __halves2bfloat162(h2, h3);
    lp[0] = __halves2bfloat162(__float2bfloat16(y0 - __bfloat162float(h0)),
                               __float2bfloat16(y1 - __bfloat162float(h1)));
    lp[1] = __halves2bfloat162(__float2bfloat16(y2 - __bfloat162float(h2)),
                               __float2bfloat16(y3 - __bfloat162float(h3)));
}

// ---------------- mma.sync bf16-split GEMM ----------------
// C[M,N] = A[M,K] @ Bt[N,K]^T, fp32 accum, 3-pass hi/lo split.
// CTA tile 128x128xBK32, 8 warps (warp tile 64x32), 3-stage cp.async.
#define BM 128
#define BN 128
#define BK 32
#define STAGES 3
#define ROWB 80                  // padded smem row stride (bytes) for 32 bf16
#define MATB (128*ROWB)          // 10240 bytes per matrix tile
#define STAGEB (4*MATB)          // Ahi, Alo, Bhi, Blo
#define SMEMB (STAGES*STAGEB)    // 122880 bytes

template<bool BIAS, bool RELU, bool RES, bool OUTF32, bool OUTBF16>
__global__ __launch_bounds__(256) void mma_gemm(
    const __nv_bfloat16* __restrict__ Ahi, const __nv_bfloat16* __restrict__ Alo,
    const __nv_bfloat16* __restrict__ Bhi, const __nv_bfloat16* __restrict__ Blo,
    const float* __restrict__ bias, const float* __restrict__ res,
    float* __restrict__ Cf, __nv_bfloat16* __restrict__ Chi,
    __nv_bfloat16* __restrict__ Clo, int M, int N, int K)
{
    extern __shared__ char smem[];
    const uint32_t sb = smem_u32(smem);
    const int tid = threadIdx.x;
    const int warp = tid >> 5, lane = tid & 31;
    const int n0 = blockIdx.x * BN, m0 = blockIdx.y * BM;
    const int Ku4 = K >> 3;
    const int nch = K / BK;

    const uint4* srcs[4] = { (const uint4*)Ahi, (const uint4*)Alo,
                             (const uint4*)Bhi, (const uint4*)Blo };

    // Issue one pipeline group. If kc >= nch, commit an EMPTY group so the
    // in-flight group count stays constant and wait_group 1 always retires
    // exactly the stage about to be consumed (tail-correctness invariant).
    auto issue = [&](int kc, int s) {
        if (kc < nch) {
            const uint32_t stage = sb + (uint32_t)s * STAGEB;
            #pragma unroll
            for (int q = 0; q < 8; q++) {
                const int idx = q * 256 + tid;
                const int mat = idx >> 9;            // 512 chunks per matrix
                const int wi  = idx & 511;
                const int row = wi >> 2, u = wi & 3;
                const int r0 = (mat < 2) ? m0 : n0;
                const uint4* g = srcs[mat] + (size_t)(r0 + row) * Ku4 + kc * 4 + u;
                const uint32_t sa = stage + mat * MATB + row * ROWB + u * 16;
                asm volatile("cp.async.cg.shared.global [%0], [%1], 16;"
                             :: "r"(sa), "l"(g));
            }
        }
        asm volatile("cp.async.commit_group;" ::: "memory");
    };

    float acc[4][4][4];
    #pragma unroll
    for (int i = 0; i < 4; i++)
        #pragma unroll
        for (int j = 0; j < 4; j++)
            #pragma unroll
            for (int r = 0; r < 4; r++) acc[i][j][r] = 0.f;

    const int wm = (warp >> 2) * 64;   // warp row offset in CTA tile
    const int wn = (warp & 3) * 32;    // warp col offset

    issue(0, 0);
    issue(1, 1);

    for (int kc = 0; kc < nch; kc++) {
        const int s = kc % STAGES;
        // entering here: groups {kc, kc+1} in flight (kc+1 may be empty)
        asm volatile("cp.async.wait_group 1;" ::: "memory");   // retires kc
        __syncthreads();
        issue(kc + 2, (kc + 2) % STAGES);                      // real or empty

        const uint32_t stage = sb + (uint32_t)s * STAGEB;
        const uint32_t aBaseH = stage;
        const uint32_t aBaseL = stage + MATB;
        const uint32_t bBaseH = stage + 2 * MATB;
        const uint32_t bBaseL = stage + 3 * MATB;

        #pragma unroll
        for (int ks = 0; ks < 2; ks++) {
            uint32_t ah[4][4], al[4][4], bh[4][2], bl[4][2];
            // A fragments: 4 m-tiles of m16k16
            const int amat = lane >> 3;
            const int arr  = ((amat & 1) << 3) + (lane & 7);
            const int au   = ks * 2 + (amat >> 1);
            #pragma unroll
            for (int i = 0; i < 4; i++) {
                const uint32_t off = (uint32_t)((wm + i * 16 + arr) * ROWB + au * 16);
                ldsm4(ah[i], aBaseH + off);
                ldsm4(al[i], aBaseL + off);
            }
            // B fragments: 4 n-tiles of n8k16 (loaded as 2 x4 pairs)
            const int bmat = lane >> 3;
            const int bu   = ks * 2 + (bmat & 1);
            const int brr  = ((bmat >> 1) << 3) + (lane & 7);
            #pragma unroll
            for (int jp = 0; jp < 2; jp++) {
                const uint32_t off = (uint32_t)((wn + jp * 16 + brr) * ROWB + bu * 16);
                uint32_t t[4];
                ldsm4(t, bBaseH + off);
                bh[jp*2][0] = t[0]; bh[jp*2][1] = t[1];
                bh[jp*2+1][0] = t[2]; bh[jp*2+1][1] = t[3];
                ldsm4(t, bBaseL + off);
                bl[jp*2][0] = t[0]; bl[jp*2][1] = t[1];
                bl[jp*2+1][0] = t[2]; bl[jp*2+1][1] = t[3];
            }
            // 3 passes: hi*hi, hi*lo, lo*hi
            #pragma unroll
            for (int i = 0; i < 4; i++)
                #pragma unroll
                for (int j = 0; j < 4; j++) mma16816(acc[i][j], ah[i], bh[j]);
            #pragma unroll
            for (int i = 0; i < 4; i++)
                #pragma unroll
                for (int j = 0; j < 4; j++) mma16816(acc[i][j], ah[i], bl[j]);
            #pragma unroll
            for (int i = 0; i < 4; i++)
                #pragma unroll
                for (int j = 0; j < 4; j++) mma16816(acc[i][j], al[i], bh[j]);
        }
        __syncthreads();
    }
    asm volatile("cp.async.wait_group 0;" ::: "memory");

    // ---------------- epilogue ----------------
    const int qrow = lane >> 2, qcol = (lane & 3) * 2;
    #pragma unroll
    for (int i = 0; i < 4; i++) {
        #pragma unroll
        for (int j = 0; j < 4; j++) {
            const int col = n0 + wn + j * 8 + qcol;
            float2 bv = make_float2(0.f, 0.f);
            if (BIAS) bv = *(const float2*)(bias + col);
            #pragma unroll
            for (int half = 0; half < 2; half++) {
                const int row = m0 + wm + i * 16 + qrow + half * 8;
                float v0 = acc[i][j][half * 2 + 0];
                float v1 = acc[i][j][half * 2 + 1];
                if (BIAS) { v0 += bv.x; v1 += bv.y; }
                if (RELU) { v0 = fmaxf(v0, 0.f); v1 = fmaxf(v1, 0.f); }
                if (RES) {
                    float2 r = *(const float2*)(res + (size_t)row * N + col);
                    v0 += r.x; v1 += r.y;
                }
                if (OUTF32) {
                    *(float2*)(Cf + (size_t)row * N + col) = make_float2(v0, v1);
                }
                if (OUTBF16) {
                    const __nv_bfloat16 h0 = __float2bfloat16(v0);
                    const __nv_bfloat16 h1 = __float2bfloat16(v1);
                    *(__nv_bfloat162*)(Chi + (size_t)row * N + col) =
                        __halves2bfloat162(h0, h1);
                    *(__nv_bfloat162*)(Clo + (size_t)row * N + col) =
                        __halves2bfloat162(
                            __float2bfloat16(v0 - __bfloat162float(h0)),
                            __float2bfloat16(v1 - __bfloat162float(h1)));
                }
            }
        }
    }
}

// ---------------- causal flash attention (fp32, writes bf16 hi/lo) ----------------
__global__ __launch_bounds__(64) void attn_kernel(
    const float* __restrict__ Q, const float* __restrict__ K,
    const float* __restrict__ V, __nv_bfloat16* __restrict__ Ohi,
    __nv_bfloat16* __restrict__ Olo)
{
    const int bh = blockIdx.y;
    const int b = bh >> 4, h = bh & 15;
    const int m0 = blockIdx.x * 64;
    const int tid = threadIdx.x;
    const size_t base = (size_t)b * TT * NE + h * HS;

    __shared__ float qs[64][65];
    __shared__ float ks[64][64];
    __shared__ float vs[64][64];

    for (int i = tid; i < 64 * 16; i += 64) {
        const int r = i >> 4, c4 = i & 15;
        float4 t = *(const float4*)(Q + base + (size_t)(m0 + r) * NE + c4 * 4);
        qs[r][c4*4+0] = t.x; qs[r][c4*4+1] = t.y;
        qs[r][c4*4+2] = t.z; qs[r][c4*4+3] = t.w;
    }
    __syncthreads();

    float qreg[HS], o[HS];
    const float scale = 0.03125f;
    #pragma unroll
    for (int d = 0; d < HS; d++) { qreg[d] = qs[tid][d] * scale; o[d] = 0.f; }
    float mi = -1e30f, li = 0.f;
    const int mq = m0 + tid;
    const int ntiles = blockIdx.x + 1;

    for (int t = 0; t < ntiles; t++) {
        const int k0 = t * 64;
        __syncthreads();
        for (int i = tid; i < 64 * 16; i += 64) {
            const int r = i >> 4, c4 = i & 15;
            *(float4*)&ks[r][c4*4] = *(const float4*)(K + base + (size_t)(k0 + r) * NE + c4 * 4);
            *(float4*)&vs[r][c4*4] = *(const float4*)(V + base + (size_t)(k0 + r) * NE + c4 * 4);
        }
        __syncthreads();

        #pragma unroll 1
        for (int c = 0; c < 64; c += 16) {
            float s[16];
            #pragma unroll
            for (int j = 0; j < 16; j++) {
                float acc = 0.f;
                #pragma unroll
                for (int d = 0; d < HS; d++) acc = fmaf(qreg[d], ks[c + j][d], acc);
                s[j] = (k0 + c + j <= mq) ? acc : -1e30f;
            }
            float mnew = mi;
            #pragma unroll
            for (int j = 0; j < 16; j++) mnew = fmaxf(mnew, s[j]);
            const float corr = __expf(mi - mnew);
            li *= corr;
            #pragma unroll
            for (int d = 0; d < HS; d++) o[d] *= corr;
            #pragma unroll
            for (int j = 0; j < 16; j++) { s[j] = __expf(s[j] - mnew); li += s[j]; }
            #pragma unroll
            for (int j = 0; j < 16; j++)
                #pragma unroll
                for (int d = 0; d < HS; d++) o[d] = fmaf(s[j], vs[c + j][d], o[d]);
            mi = mnew;
        }
    }

    const float inv = 1.0f / li;
    __syncthreads();
    #pragma unroll
    for (int d = 0; d < HS; d++) qs[tid][d] = o[d] * inv;
    __syncthreads();
    for (int i = tid; i < 64 * 16; i += 64) {
        const int r = i >> 4, c4 = i & 15;
        const float x0 = qs[r][c4*4+0], x1 = qs[r][c4*4+1];
        const float x2 = qs[r][c4*4+2], x3 = qs[r][c4*4+3];
        const __nv_bfloat16 h0 = __float2bfloat16(x0), h1 = __float2bfloat16(x1);
        const __nv_bfloat16 h2 = __float2bfloat16(x2), h3 = __float2bfloat16(x3);
        const size_t off = base + (size_t)(m0 + r) * NE + c4 * 4;
        __nv_bfloat162* hp = (__nv_bfloat162*)(Ohi + off);
        __nv_bfloat162* lp = (__nv_bfloat162*)(Olo + off);
        hp[0] = __halves2bfloat162(h0, h1);
        hp[1] = __halves2bfloat162(h2, h3);
        lp[0] = __halves2bfloat162(__float2bfloat16(x0 - __bfloat162float(h0)),
                                   __float2bfloat16(x1 - __bfloat162float(h1)));
        lp[1] = __halves2bfloat162(__float2bfloat16(x2 - __bfloat162float(h2)),
                                   __float2bfloat16(x3 - __bfloat162float(h3)));
    }
}

// ---------------- launch ----------------
extern "C" void kernel_launch(void* const* d_in, const int* in_sizes, int n_in,
                              void* d_out, int out_size)
{
    const float* x  = (const float*)d_in[0];
    const float* Wq = (const float*)d_in[1];
    const float* Wk = (const float*)d_in[2];
    const float* Wv = (const float*)d_in[3];
    const float* Wo = (const float*)d_in[4];
    const float* bo = (const float*)d_in[5];
    const float* W1 = (const float*)d_in[6];
    const float* b1 = (const float*)d_in[7];
    const float* W2 = (const float*)d_in[8];
    const float* b2 = (const float*)d_in[9];
    const float* g1  = (const float*)d_in[10];
    const float* be1 = (const float*)d_in[11];
    const float* g2  = (const float*)d_in[12];
    const float* be2 = (const float*)d_in[13];
    float* out = (float*)d_out;

    __nv_bfloat16 *h_hi, *h_lo, *at_hi, *at_lo, *ff_hi, *ff_lo;
    __nv_bfloat16 *wq_hi, *wq_lo, *wk_hi, *wk_lo, *wv_hi, *wv_lo;
    __nv_bfloat16 *wo_hi, *wo_lo, *w1_hi, *w1_lo, *w2_hi, *w2_lo;
    float *q, *k, *v;
    cudaGetSymbolAddress((void**)&h_hi, g_h_hi);   cudaGetSymbolAddress((void**)&h_lo, g_h_lo);
    cudaGetSymbolAddress((void**)&q, g_q);         cudaGetSymbolAddress((void**)&k, g_k);
    cudaGetSymbolAddress((void**)&v, g_v);
    cudaGetSymbolAddress((void**)&at_hi, g_at_hi); cudaGetSymbolAddress((void**)&at_lo, g_at_lo);
    cudaGetSymbolAddress((void**)&ff_hi, g_ff_hi); cudaGetSymbolAddress((void**)&ff_lo, g_ff_lo);
    cudaGetSymbolAddress((void**)&wq_hi, g_wq_hi); cudaGetSymbolAddress((void**)&wq_lo, g_wq_lo);
    cudaGetSymbolAddress((void**)&wk_hi, g_wk_hi); cudaGetSymbolAddress((void**)&wk_lo, g_wk_lo);
    cudaGetSymbolAddress((void**)&wv_hi, g_wv_hi); cudaGetSymbolAddress((void**)&wv_lo, g_wv_lo);
    cudaGetSymbolAddress((void**)&wo_hi, g_wo_hi); cudaGetSymbolAddress((void**)&wo_lo, g_wo_lo);
    cudaGetSymbolAddress((void**)&w1_hi, g_w1_hi); cudaGetSymbolAddress((void**)&w1_lo, g_w1_lo);
    cudaGetSymbolAddress((void**)&w2_hi, g_w2_hi); cudaGetSymbolAddress((void**)&w2_lo, g_w2_lo);

    cudaFuncSetAttribute(mma_gemm<false,false,false,true,false>,
                         cudaFuncAttributeMaxDynamicSharedMemorySize, SMEMB);
    cudaFuncSetAttribute(mma_gemm<true,false,true,true,false>,
                         cudaFuncAttributeMaxDynamicSharedMemorySize, SMEMB);
    cudaFuncSetAttribute(mma_gemm<true,true,false,false,true>,
                         cudaFuncAttributeMaxDynamicSharedMemorySize, SMEMB);

    // 0) transpose + split weights
    wsplit_kernel<<<dim3(NE/32, NE/32), 256>>>(Wq, wq_hi, wq_lo, NE, NE);
    wsplit_kernel<<<dim3(NE/32, NE/32), 256>>>(Wk, wk_hi, wk_lo, NE, NE);
    wsplit_kernel<<<dim3(NE/32, NE/32), 256>>>(Wv, wv_hi, wv_lo, NE, NE);
    wsplit_kernel<<<dim3(NE/32, NE/32), 256>>>(Wo, wo_hi, wo_lo, NE, NE);
    wsplit_kernel<<<dim3(FF/32, NE/32), 256>>>(W1, w1_hi, w1_lo, NE, FF);
    wsplit_kernel<<<dim3(NE/32, FF/32), 256>>>(W2, w2_hi, w2_lo, FF, NE);

    // 1) h = ln1(x) -> bf16 hi/lo
    ln_kernel<<<BT, 256>>>(x, g1, be1, h_hi, h_lo);

    // 2) q,k,v = h @ W{q,k,v}  (fp32 out)
    dim3 gQKV(NE/128, BT/128);
    mma_gemm<false,false,false,true,false><<<gQKV, 256, SMEMB>>>(
        h_hi, h_lo, wq_hi, wq_lo, nullptr, nullptr, q, nullptr, nullptr, BT, NE, NE);
    mma_gemm<false,false,false,true,false><<<gQKV, 256, SMEMB>>>(
        h_hi, h_lo, wk_hi, wk_lo, nullptr, nullptr, k, nullptr, nullptr, BT, NE, NE);
    mma_gemm<false,false,false,true,false><<<gQKV, 256, SMEMB>>>(
        h_hi, h_lo, wv_hi, wv_lo, nullptr, nullptr, v, nullptr, nullptr, BT, NE, NE);

    // 3) causal flash attention -> bf16 hi/lo
    dim3 gAtt(TT/64, BB*NH);
    attn_kernel<<<gAtt, 64>>>(q, k, v, at_hi, at_lo);

    // 4) out = attn @ Wo + bo + x
    mma_gemm<true,false,true,true,false><<<gQKV, 256, SMEMB>>>(
        at_hi, at_lo, wo_hi, wo_lo, bo, x, out, nullptr, nullptr, BT, NE, NE);

    // 5) h = ln2(out)
    ln_kernel<<<BT, 256>>>(out, g2, be2, h_hi, h_lo);

    // 6) ff = relu(h @ W1 + b1) -> bf16 hi/lo
    dim3 gF1(FF/128, BT/128);
    mma_gemm<true,true,false,false,true><<<gF1, 256, SMEMB>>>(
        h_hi, h_lo, w1_hi, w1_lo, b1, nullptr, nullptr, ff_hi, ff_lo, BT, FF, NE);

    // 7) out = ff @ W2 + b2 + out
    dim3 gF2(NE/128, BT/128);
    mma_gemm<true,false,true,true,false><<<gF2, 256, SMEMB>>>(
        ff_hi, ff_lo, w2_hi, w2_lo, b2, out, out, nullptr, nullptr, BT, NE, FF);
}

// round 8
// speedup vs baseline: 4.6361x; 1.5566x over previous
#include <cuda_runtime.h>
#include <cuda_bf16.h>
#include <cstdint>
#include <math.h>

// Problem constants
#define NE    1024
#define NH    16
#define HS    64
#define TT    2048
#define BB    2
#define BT    (BB*TT)   // 4096
#define FF    4096
#define LN_EPS 1e-5f

// ---------------- scratch (device globals) ----------------
__device__ __nv_bfloat16 g_h_hi[(size_t)BT*NE], g_h_lo[(size_t)BT*NE];
__device__ __nv_bfloat16 g_q_hi[(size_t)BT*NE], g_q_lo[(size_t)BT*NE];
__device__ __nv_bfloat16 g_k_hi[(size_t)BT*NE], g_k_lo[(size_t)BT*NE];
__device__ __nv_bfloat16 g_v_hi[(size_t)BT*NE], g_v_lo[(size_t)BT*NE];
__device__ __nv_bfloat16 g_at_hi[(size_t)BT*NE], g_at_lo[(size_t)BT*NE];
__device__ __nv_bfloat16 g_ff_hi[(size_t)BT*FF], g_ff_lo[(size_t)BT*FF];
// transposed+split weights: [N,K] K-major
__device__ __nv_bfloat16 g_wq_hi[NE*NE], g_wq_lo[NE*NE];
__device__ __nv_bfloat16 g_wk_hi[NE*NE], g_wk_lo[NE*NE];
__device__ __nv_bfloat16 g_wv_hi[NE*NE], g_wv_lo[NE*NE];
__device__ __nv_bfloat16 g_wo_hi[NE*NE], g_wo_lo[NE*NE];
__device__ __nv_bfloat16 g_w1_hi[(size_t)NE*FF], g_w1_lo[(size_t)NE*FF];
__device__ __nv_bfloat16 g_w2_hi[(size_t)NE*FF], g_w2_lo[(size_t)NE*FF];

// ---------------- PTX helpers ----------------
__device__ __forceinline__ uint32_t smem_u32(const void* p) {
    uint32_t a;
    asm("{ .reg .u64 t; cvta.to.shared.u64 t, %1; cvt.u32.u64 %0, t; }" : "=r"(a) : "l"(p));
    return a;
}

__device__ __forceinline__ void ldsm4(uint32_t* r, uint32_t addr) {
    asm volatile("ldmatrix.sync.aligned.m8n8.x4.shared.b16 {%0,%1,%2,%3}, [%4];"
        : "=r"(r[0]), "=r"(r[1]), "=r"(r[2]), "=r"(r[3]) : "r"(addr));
}

__device__ __forceinline__ void ldsm4t(uint32_t* r, uint32_t addr) {
    asm volatile("ldmatrix.sync.aligned.m8n8.x4.trans.shared.b16 {%0,%1,%2,%3}, [%4];"
        : "=r"(r[0]), "=r"(r[1]), "=r"(r[2]), "=r"(r[3]) : "r"(addr));
}

__device__ __forceinline__ void mma16816(float* c, const uint32_t* a, const uint32_t* b) {
    asm volatile("mma.sync.aligned.m16n8k16.row.col.f32.bf16.bf16.f32 "
        "{%0,%1,%2,%3}, {%4,%5,%6,%7}, {%8,%9}, {%0,%1,%2,%3};"
        : "+f"(c[0]), "+f"(c[1]), "+f"(c[2]), "+f"(c[3])
        : "r"(a[0]), "r"(a[1]), "r"(a[2]), "r"(a[3]), "r"(b[0]), "r"(b[1]));
}

__device__ __forceinline__ uint32_t packbf(float a, float b) {
    __nv_bfloat162 t = __halves2bfloat162(__float2bfloat16(a), __float2bfloat16(b));
    return *(uint32_t*)&t;
}

// ---------------- weight transpose + bf16 split ----------------
__global__ __launch_bounds__(256) void wsplit_kernel(
    const float* __restrict__ W, __nv_bfloat16* __restrict__ Thi,
    __nv_bfloat16* __restrict__ Tlo, int K, int N)
{
    __shared__ float t[32][33];
    const int tx = threadIdx.x & 31, ty = threadIdx.x >> 5;
    const int nb = blockIdx.x * 32, kb = blockIdx.y * 32;
    #pragma unroll
    for (int i = 0; i < 4; i++) {
        const int k = kb + ty + i * 8;
        t[ty + i * 8][tx] = W[(size_t)k * N + nb + tx];
    }
    __syncthreads();
    #pragma unroll
    for (int i = 0; i < 4; i++) {
        const int n = nb + ty + i * 8;
        const float v = t[tx][ty + i * 8];
        const __nv_bfloat16 h = __float2bfloat16(v);
        Thi[(size_t)n * K + kb + tx] = h;
        Tlo[(size_t)n * K + kb + tx] = __float2bfloat16(v - __bfloat162float(h));
    }
}

// ---------------- LayerNorm -> bf16 hi/lo ----------------
__global__ __launch_bounds__(256) void ln_kernel(
    const float* __restrict__ X, const float* __restrict__ G,
    const float* __restrict__ Be, __nv_bfloat16* __restrict__ Yhi,
    __nv_bfloat16* __restrict__ Ylo)
{
    const int row = blockIdx.x;
    const float* xr = X + (size_t)row * NE;
    const int tid = threadIdx.x;

    float4 xv = ((const float4*)xr)[tid];
    float s  = xv.x + xv.y + xv.z + xv.w;
    float ss = xv.x*xv.x + xv.y*xv.y + xv.z*xv.z + xv.w*xv.w;

    __shared__ float red_s[32], red_q[32];
    const int lane = tid & 31, wid = tid >> 5;
    #pragma unroll
    for (int o = 16; o > 0; o >>= 1) {
        s  += __shfl_xor_sync(0xffffffffu, s, o);
        ss += __shfl_xor_sync(0xffffffffu, ss, o);
    }
    if (lane == 0) { red_s[wid] = s; red_q[wid] = ss; }
    __syncthreads();
    if (wid == 0) {
        s  = (lane < 8) ? red_s[lane] : 0.f;
        ss = (lane < 8) ? red_q[lane] : 0.f;
        #pragma unroll
        for (int o = 4; o > 0; o >>= 1) {
            s  += __shfl_xor_sync(0xffffffffu, s, o);
            ss += __shfl_xor_sync(0xffffffffu, ss, o);
        }
        if (lane == 0) { red_s[0] = s; red_q[0] = ss; }
    }
    __syncthreads();
    const float mu   = red_s[0] * (1.0f / NE);
    const float var  = red_q[0] * (1.0f / NE) - mu * mu;
    const float rstd = rsqrtf(var + LN_EPS);

    float4 gv = ((const float4*)G)[tid];
    float4 bv = ((const float4*)Be)[tid];
    float y0 = (xv.x - mu) * rstd * gv.x + bv.x;
    float y1 = (xv.y - mu) * rstd * gv.y + bv.y;
    float y2 = (xv.z - mu) * rstd * gv.z + bv.z;
    float y3 = (xv.w - mu) * rstd * gv.w + bv.w;

    __nv_bfloat16 h0 = __float2bfloat16(y0), h1 = __float2bfloat16(y1);
    __nv_bfloat16 h2 = __float2bfloat16(y2), h3 = __float2bfloat16(y3);
    __nv_bfloat162* hp = (__nv_bfloat162*)(Yhi + (size_t)row * NE + tid * 4);
    __nv_bfloat162* lp = (__nv_bfloat162*)(Ylo + (size_t)row * NE + tid * 4);
    hp[0] = __halves2bfloat162(h0, h1);
    hp[1] = __halves2bfloat162(h2, h3);
    lp[0] = __halves2bfloat162(__float2bfloat16(y0 - __bfloat162float(h0)),
                               __float2bfloat16(y1 - __bfloat162float(h1)));
    lp[1] = __halves2bfloat162(__float2bfloat16(y2 - __bfloat162float(h2)),
                               __float2bfloat16(y3 - __bfloat162float(h3)));
}

// ---------------- mma.sync bf16-split GEMM (unchanged from R7 pass) ----------------
#define BM 128
#define BN 128
#define BK 32
#define STAGES 3
#define ROWB 80
#define MATB (128*ROWB)
#define STAGEB (4*MATB)
#define SMEMB (STAGES*STAGEB)

template<bool BIAS, bool RELU, bool RES, bool OUTF32, bool OUTBF16>
__global__ __launch_bounds__(256) void mma_gemm(
    const __nv_bfloat16* __restrict__ Ahi, const __nv_bfloat16* __restrict__ Alo,
    const __nv_bfloat16* __restrict__ Bhi, const __nv_bfloat16* __restrict__ Blo,
    const float* __restrict__ bias, const float* __restrict__ res,
    float* __restrict__ Cf, __nv_bfloat16* __restrict__ Chi,
    __nv_bfloat16* __restrict__ Clo, int M, int N, int K)
{
    extern __shared__ char smem[];
    const uint32_t sb = smem_u32(smem);
    const int tid = threadIdx.x;
    const int warp = tid >> 5, lane = tid & 31;
    const int n0 = blockIdx.x * BN, m0 = blockIdx.y * BM;
    const int Ku4 = K >> 3;
    const int nch = K / BK;

    const uint4* srcs[4] = { (const uint4*)Ahi, (const uint4*)Alo,
                             (const uint4*)Bhi, (const uint4*)Blo };

    auto issue = [&](int kc, int s) {
        if (kc < nch) {
            const uint32_t stage = sb + (uint32_t)s * STAGEB;
            #pragma unroll
            for (int q = 0; q < 8; q++) {
                const int idx = q * 256 + tid;
                const int mat = idx >> 9;
                const int wi  = idx & 511;
                const int row = wi >> 2, u = wi & 3;
                const int r0 = (mat < 2) ? m0 : n0;
                const uint4* g = srcs[mat] + (size_t)(r0 + row) * Ku4 + kc * 4 + u;
                const uint32_t sa = stage + mat * MATB + row * ROWB + u * 16;
                asm volatile("cp.async.cg.shared.global [%0], [%1], 16;"
                             :: "r"(sa), "l"(g));
            }
        }
        asm volatile("cp.async.commit_group;" ::: "memory");
    };

    float acc[4][4][4];
    #pragma unroll
    for (int i = 0; i < 4; i++)
        #pragma unroll
        for (int j = 0; j < 4; j++)
            #pragma unroll
            for (int r = 0; r < 4; r++) acc[i][j][r] = 0.f;

    const int wm = (warp >> 2) * 64;
    const int wn = (warp & 3) * 32;

    issue(0, 0);
    issue(1, 1);

    for (int kc = 0; kc < nch; kc++) {
        const int s = kc % STAGES;
        asm volatile("cp.async.wait_group 1;" ::: "memory");
        __syncthreads();
        issue(kc + 2, (kc + 2) % STAGES);

        const uint32_t stage = sb + (uint32_t)s * STAGEB;
        const uint32_t aBaseH = stage;
        const uint32_t aBaseL = stage + MATB;
        const uint32_t bBaseH = stage + 2 * MATB;
        const uint32_t bBaseL = stage + 3 * MATB;

        #pragma unroll
        for (int ks = 0; ks < 2; ks++) {
            uint32_t ah[4][4], al[4][4], bh[4][2], bl[4][2];
            const int amat = lane >> 3;
            const int arr  = ((amat & 1) << 3) + (lane & 7);
            const int au   = ks * 2 + (amat >> 1);
            #pragma unroll
            for (int i = 0; i < 4; i++) {
                const uint32_t off = (uint32_t)((wm + i * 16 + arr) * ROWB + au * 16);
                ldsm4(ah[i], aBaseH + off);
                ldsm4(al[i], aBaseL + off);
            }
            const int bmat = lane >> 3;
            const int bu   = ks * 2 + (bmat & 1);
            const int brr  = ((bmat >> 1) << 3) + (lane & 7);
            #pragma unroll
            for (int jp = 0; jp < 2; jp++) {
                const uint32_t off = (uint32_t)((wn + jp * 16 + brr) * ROWB + bu * 16);
                uint32_t t[4];
                ldsm4(t, bBaseH + off);
                bh[jp*2][0] = t[0]; bh[jp*2][1] = t[1];
                bh[jp*2+1][0] = t[2]; bh[jp*2+1][1] = t[3];
                ldsm4(t, bBaseL + off);
                bl[jp*2][0] = t[0]; bl[jp*2][1] = t[1];
                bl[jp*2+1][0] = t[2]; bl[jp*2+1][1] = t[3];
            }
            #pragma unroll
            for (int i = 0; i < 4; i++)
                #pragma unroll
                for (int j = 0; j < 4; j++) mma16816(acc[i][j], ah[i], bh[j]);
            #pragma unroll
            for (int i = 0; i < 4; i++)
                #pragma unroll
                for (int j = 0; j < 4; j++) mma16816(acc[i][j], ah[i], bl[j]);
            #pragma unroll
            for (int i = 0; i < 4; i++)
                #pragma unroll
                for (int j = 0; j < 4; j++) mma16816(acc[i][j], al[i], bh[j]);
        }
        __syncthreads();
    }
    asm volatile("cp.async.wait_group 0;" ::: "memory");

    const int qrow = lane >> 2, qcol = (lane & 3) * 2;
    #pragma unroll
    for (int i = 0; i < 4; i++) {
        #pragma unroll
        for (int j = 0; j < 4; j++) {
            const int col = n0 + wn + j * 8 + qcol;
            float2 bv = make_float2(0.f, 0.f);
            if (BIAS) bv = *(const float2*)(bias + col);
            #pragma unroll
            for (int half = 0; half < 2; half++) {
                const int row = m0 + wm + i * 16 + qrow + half * 8;
                float v0 = acc[i][j][half * 2 + 0];
                float v1 = acc[i][j][half * 2 + 1];
                if (BIAS) { v0 += bv.x; v1 += bv.y; }
                if (RELU) { v0 = fmaxf(v0, 0.f); v1 = fmaxf(v1, 0.f); }
                if (RES) {
                    float2 r = *(const float2*)(res + (size_t)row * N + col);
                    v0 += r.x; v1 += r.y;
                }
                if (OUTF32) {
                    *(float2*)(Cf + (size_t)row * N + col) = make_float2(v0, v1);
                }
                if (OUTBF16) {
                    const __nv_bfloat16 h0 = __float2bfloat16(v0);
                    const __nv_bfloat16 h1 = __float2bfloat16(v1);
                    *(__nv_bfloat162*)(Chi + (size_t)row * N + col) =
                        __halves2bfloat162(h0, h1);
                    *(__nv_bfloat162*)(Clo + (size_t)row * N + col) =
                        __halves2bfloat162(
                            __float2bfloat16(v0 - __bfloat162float(h0)),
                            __float2bfloat16(v1 - __bfloat162float(h1)));
                }
            }
        }
    }
}

// ---------------- tensor-core causal flash attention ----------------
// Block: 256 threads (8 warps), one (b,h), 128-query tile. 64-key tiles,
// double-buffered cp.async. bf16-split QK (3 passes) and PV (3 passes),
// fp32 online softmax in accumulator registers.
#define AROWB 144
#define AQMAT (128*AROWB)               // 18432
#define AKMAT (64*AROWB)                // 9216
#define ASTAGE (4*AKMAT)                // 36864
#define ASMEM (2*AQMAT + 2*ASTAGE)      // 110592

__global__ __launch_bounds__(256) void attn_mma_kernel(
    const __nv_bfloat16* __restrict__ Qhi, const __nv_bfloat16* __restrict__ Qlo,
    const __nv_bfloat16* __restrict__ Kh,  const __nv_bfloat16* __restrict__ Kl,
    const __nv_bfloat16* __restrict__ Vh,  const __nv_bfloat16* __restrict__ Vl,
    __nv_bfloat16* __restrict__ Ohi, __nv_bfloat16* __restrict__ Olo)
{
    extern __shared__ char smem[];
    const uint32_t sb = smem_u32(smem);
    const int tid = threadIdx.x, warp = tid >> 5, lane = tid & 31;
    const int bh = blockIdx.y, b = bh >> 4, h = bh & 15;
    const int qt = gridDim.x - 1 - blockIdx.x;     // heavy tiles first
    const int q0 = qt * 128;
    const size_t gbase = (size_t)b * TT * NE + h * HS;

    // Q tile: 128 rows x 64 bf16 x 2 mats, 8 chunks/thread
    {
        const __nv_bfloat16* qsrc[2] = { Qhi, Qlo };
        #pragma unroll
        for (int c = 0; c < 8; c++) {
            const int idx = c * 256 + tid;
            const int mat = idx >> 10, wi = idx & 1023;
            const int row = wi >> 3, u = wi & 7;
            const uint4* g = (const uint4*)(qsrc[mat] + gbase + (size_t)(q0 + row) * NE) + u;
            const uint32_t sa = sb + mat * AQMAT + row * AROWB + u * 16;
            asm volatile("cp.async.cg.shared.global [%0], [%1], 16;" :: "r"(sa), "l"(g));
        }
        asm volatile("cp.async.commit_group;" ::: "memory");
    }

    const __nv_bfloat16* kvsrc[4] = { Kh, Kl, Vh, Vl };
    auto issue_kv = [&](int t, int s) {
        if (t >= 0) {
            const int k0 = t * 64;
            const uint32_t stage = sb + 2 * AQMAT + (uint32_t)s * ASTAGE;
            #pragma unroll
            for (int c = 0; c < 8; c++) {
                const int idx = c * 256 + tid;
                const int mat = idx >> 9, wi = idx & 511;
                const int row = wi >> 3, u = wi & 7;
                const uint4* g = (const uint4*)(kvsrc[mat] + gbase + (size_t)(k0 + row) * NE) + u;
                const uint32_t sa = stage + mat * AKMAT + row * AROWB + u * 16;
                asm volatile("cp.async.cg.shared.global [%0], [%1], 16;" :: "r"(sa), "l"(g));
            }
        }
        asm volatile("cp.async.commit_group;" ::: "memory");
    };

    const int ntiles = 2 * (qt + 1);
    issue_kv(0, 0);

    float m[2] = { -1e30f, -1e30f }, l[2] = { 0.f, 0.f };
    float o[8][4];
    #pragma unroll
    for (int nt = 0; nt < 8; nt++)
        #pragma unroll
        for (int e = 0; e < 4; e++) o[nt][e] = 0.f;

    const float scale = 0.03125f;   // 1024^-0.5, faithful to source
    const int amat = lane >> 3;
    const int arr  = ((amat & 1) << 3) + (lane & 7);
    const int ahalf = amat >> 1;
    const int brr  = ((amat >> 1) << 3) + (lane & 7);
    const int bhalf = amat & 1;
    const int vrow  = ((amat & 1) << 3) + (lane & 7);
    const int vhalf = lane >> 4;

    for (int t = 0; t < ntiles; t++) {
        issue_kv((t + 1 < ntiles) ? t + 1 : -1, (t + 1) & 1);
        asm volatile("cp.async.wait_group 1;" ::: "memory");
        __syncthreads();

        const int k0 = t * 64;
        const uint32_t stage = sb + 2 * AQMAT + (uint32_t)(t & 1) * ASTAGE;
        const uint32_t kHi = stage, kLo = stage + AKMAT;
        const uint32_t vHi = stage + 2 * AKMAT, vLo = stage + 3 * AKMAT;

        // ----- S = Q K^T, 3 split passes -----
        float s[8][4];
        #pragma unroll
        for (int nt = 0; nt < 8; nt++)
            #pragma unroll
            for (int e = 0; e < 4; e++) s[nt][e] = 0.f;

        const uint32_t aB[3] = { sb, sb, sb + AQMAT };
        const uint32_t bB[3] = { kHi, kLo, kHi };
        #pragma unroll
        for (int p = 0; p < 3; p++) {
            #pragma unroll
            for (int kc = 0; kc < 4; kc++) {
                uint32_t af[4];
                ldsm4(af, aB[p] + (uint32_t)((warp * 16 + arr) * AROWB + kc * 32 + ahalf * 16));
                #pragma unroll
                for (int jp = 0; jp < 4; jp++) {
                    uint32_t tt[4];
                    ldsm4(tt, bB[p] + (uint32_t)((jp * 16 + brr) * AROWB + kc * 32 + bhalf * 16));
                    uint32_t b0[2] = { tt[0], tt[1] }, b1[2] = { tt[2], tt[3] };
                    mma16816(s[jp * 2],     af, b0);
                    mma16816(s[jp * 2 + 1], af, b1);
                }
            }
        }

        // ----- scale + causal mask + online softmax -----
        const bool domask = (k0 + 63 > q0);
        float mnew[2] = { m[0], m[1] };
        #pragma unroll
        for (int nt = 0; nt < 8; nt++)
            #pragma unroll
            for (int e = 0; e < 4; e++) {
                float v = s[nt][e] * scale;
                if (domask) {
                    const int key = k0 + nt * 8 + (lane & 3) * 2 + (e & 1);
                    const int qq  = q0 + warp * 16 + (lane >> 2) + (e >> 1) * 8;
                    if (key > qq) v = -1e30f;
                }
                s[nt][e] = v;
                mnew[e >> 1] = fmaxf(mnew[e >> 1], v);
            }
        #pragma unroll
        for (int r = 0; r < 2; r++) {
            mnew[r] = fmaxf(mnew[r], __shfl_xor_sync(0xffffffffu, mnew[r], 1));
            mnew[r] = fmaxf(mnew[r], __shfl_xor_sync(0xffffffffu, mnew[r], 2));
        }
        float corr[2], psum[2] = { 0.f, 0.f };
        corr[0] = __expf(m[0] - mnew[0]);
        corr[1] = __expf(m[1] - mnew[1]);
        m[0] = mnew[0]; m[1] = mnew[1];
        #pragma unroll
        for (int nt = 0; nt < 8; nt++)
            #pragma unroll
            for (int e = 0; e < 4; e++) {
                const float p_ = __expf(s[nt][e] - mnew[e >> 1]);
                s[nt][e] = p_;
                psum[e >> 1] += p_;
            }
        #pragma unroll
        for (int r = 0; r < 2; r++) {
            psum[r] += __shfl_xor_sync(0xffffffffu, psum[r], 1);
            psum[r] += __shfl_xor_sync(0xffffffffu, psum[r], 2);
            l[r] = l[r] * corr[r] + psum[r];
        }
        #pragma unroll
        for (int nt = 0; nt < 8; nt++)
            #pragma unroll
            for (int e = 0; e < 4; e++) o[nt][e] *= corr[e >> 1];

        // ----- O += P V, 3 split passes -----
        #pragma unroll
        for (int kk = 0; kk < 4; kk++) {
            uint32_t phi[4], plo[4];
            {
                const float c0 = s[2*kk][0],   c1 = s[2*kk][1];
                const float c2 = s[2*kk][2],   c3 = s[2*kk][3];
                const float d0 = s[2*kk+1][0], d1 = s[2*kk+1][1];
                const float d2 = s[2*kk+1][2], d3 = s[2*kk+1][3];
                phi[0] = packbf(c0, c1); phi[1] = packbf(c2, c3);
                phi[2] = packbf(d0, d1); phi[3] = packbf(d2, d3);
                plo[0] = packbf(c0 - __bfloat162float(__float2bfloat16(c0)),
                                c1 - __bfloat162float(__float2bfloat16(c1)));
                plo[1] = packbf(c2 - __bfloat162float(__float2bfloat16(c2)),
                                c3 - __bfloat162float(__float2bfloat16(c3)));
                plo[2] = packbf(d0 - __bfloat162float(__float2bfloat16(d0)),
                                d1 - __bfloat162float(__float2bfloat16(d1)));
                plo[3] = packbf(d2 - __bfloat162float(__float2bfloat16(d2)),
                                d3 - __bfloat162float(__float2bfloat16(d3)));
            }
            #pragma unroll
            for (int jp = 0; jp < 4; jp++) {
                const uint32_t va =
                    (uint32_t)((kk * 16 + vrow) * AROWB + jp * 32 + vhalf * 16);
                uint32_t th[4], tl[4];
                ldsm4t(th, vHi + va);
                ldsm4t(tl, vLo + va);
                uint32_t bh0[2] = { th[0], th[1] }, bh1[2] = { th[2], th[3] };
                uint32_t bl0[2] = { tl[0], tl[1] }, bl1[2] = { tl[2], tl[3] };
                mma16816(o[jp*2],   phi, bh0);
                mma16816(o[jp*2+1], phi, bh1);
                mma16816(o[jp*2],   phi, bl0);
                mma16816(o[jp*2+1], phi, bl1);
                mma16816(o[jp*2],   plo, bh0);
                mma16816(o[jp*2+1], plo, bh1);
            }
        }
        __syncthreads();   // stage consumed; safe to refill next iter
    }

    // ----- epilogue: O / l -> bf16 hi/lo -----
    const float inv0 = 1.0f / l[0], inv1 = 1.0f / l[1];
    const int r0 = q0 + warp * 16 + (lane >> 2);
    const int r1 = r0 + 8;
    #pragma unroll
    for (int nt = 0; nt < 8; nt++) {
        const int col = nt * 8 + (lane & 3) * 2;
        const float v0 = o[nt][0] * inv0, v1 = o[nt][1] * inv0;
        const float v2 = o[nt][2] * inv1, v3 = o[nt][3] * inv1;
        const size_t off0 = gbase + (size_t)r0 * NE + col;
        const size_t off1 = gbase + (size_t)r1 * NE + col;
        const __nv_bfloat16 a0 = __float2bfloat16(v0), a1 = __float2bfloat16(v1);
        const __nv_bfloat16 a2 = __float2bfloat16(v2), a3 = __float2bfloat16(v3);
        *(__nv_bfloat162*)(Ohi + off0) = __halves2bfloat162(a0, a1);
        *(__nv_bfloat162*)(Ohi + off1) = __halves2bfloat162(a2, a3);
        *(__nv_bfloat162*)(Olo + off0) = __halves2bfloat162(
            __float2bfloat16(v0 - __bfloat162float(a0)),
            __float2bfloat16(v1 - __bfloat162float(a1)));
        *(__nv_bfloat162*)(Olo + off1) = __halves2bfloat162(
            __float2bfloat16(v2 - __bfloat162float(a2)),
            __float2bfloat16(v3 - __bfloat162float(a3)));
    }
}

// ---------------- launch ----------------
extern "C" void kernel_launch(void* const* d_in, const int* in_sizes, int n_in,
                              void* d_out, int out_size)
{
    const float* x  = (const float*)d_in[0];
    const float* Wq = (const float*)d_in[1];
    const float* Wk = (const float*)d_in[2];
    const float* Wv = (const float*)d_in[3];
    const float* Wo = (const float*)d_in[4];
    const float* bo = (const float*)d_in[5];
    const float* W1 = (const float*)d_in[6];
    const float* b1 = (const float*)d_in[7];
    const float* W2 = (const float*)d_in[8];
    const float* b2 = (const float*)d_in[9];
    const float* g1  = (const float*)d_in[10];
    const float* be1 = (const float*)d_in[11];
    const float* g2  = (const float*)d_in[12];
    const float* be2 = (const float*)d_in[13];
    float* out = (float*)d_out;

    __nv_bfloat16 *h_hi, *h_lo, *at_hi, *at_lo, *ff_hi, *ff_lo;
    __nv_bfloat16 *q_hi, *q_lo, *k_hi, *k_lo, *v_hi, *v_lo;
    __nv_bfloat16 *wq_hi, *wq_lo, *wk_hi, *wk_lo, *wv_hi, *wv_lo;
    __nv_bfloat16 *wo_hi, *wo_lo, *w1_hi, *w1_lo, *w2_hi, *w2_lo;
    cudaGetSymbolAddress((void**)&h_hi, g_h_hi);   cudaGetSymbolAddress((void**)&h_lo, g_h_lo);
    cudaGetSymbolAddress((void**)&q_hi, g_q_hi);   cudaGetSymbolAddress((void**)&q_lo, g_q_lo);
    cudaGetSymbolAddress((void**)&k_hi, g_k_hi);   cudaGetSymbolAddress((void**)&k_lo, g_k_lo);
    cudaGetSymbolAddress((void**)&v_hi, g_v_hi);   cudaGetSymbolAddress((void**)&v_lo, g_v_lo);
    cudaGetSymbolAddress((void**)&at_hi, g_at_hi); cudaGetSymbolAddress((void**)&at_lo, g_at_lo);
    cudaGetSymbolAddress((void**)&ff_hi, g_ff_hi); cudaGetSymbolAddress((void**)&ff_lo, g_ff_lo);
    cudaGetSymbolAddress((void**)&wq_hi, g_wq_hi); cudaGetSymbolAddress((void**)&wq_lo, g_wq_lo);
    cudaGetSymbolAddress((void**)&wk_hi, g_wk_hi); cudaGetSymbolAddress((void**)&wk_lo, g_wk_lo);
    cudaGetSymbolAddress((void**)&wv_hi, g_wv_hi); cudaGetSymbolAddress((void**)&wv_lo, g_wv_lo);
    cudaGetSymbolAddress((void**)&wo_hi, g_wo_hi); cudaGetSymbolAddress((void**)&wo_lo, g_wo_lo);
    cudaGetSymbolAddress((void**)&w1_hi, g_w1_hi); cudaGetSymbolAddress((void**)&w1_lo, g_w1_lo);
    cudaGetSymbolAddress((void**)&w2_hi, g_w2_hi); cudaGetSymbolAddress((void**)&w2_lo, g_w2_lo);

    cudaFuncSetAttribute(mma_gemm<false,false,false,false,true>,
                         cudaFuncAttributeMaxDynamicSharedMemorySize, SMEMB);
    cudaFuncSetAttribute(mma_gemm<true,false,true,true,false>,
                         cudaFuncAttributeMaxDynamicSharedMemorySize, SMEMB);
    cudaFuncSetAttribute(mma_gemm<true,true,false,false,true>,
                         cudaFuncAttributeMaxDynamicSharedMemorySize, SMEMB);
    cudaFuncSetAttribute(attn_mma_kernel,
                         cudaFuncAttributeMaxDynamicSharedMemorySize, ASMEM);

    // 0) transpose + split weights
    wsplit_kernel<<<dim3(NE/32, NE/32), 256>>>(Wq, wq_hi, wq_lo, NE, NE);
    wsplit_kernel<<<dim3(NE/32, NE/32), 256>>>(Wk, wk_hi, wk_lo, NE, NE);
    wsplit_kernel<<<dim3(NE/32, NE/32), 256>>>(Wv, wv_hi, wv_lo, NE, NE);
    wsplit_kernel<<<dim3(NE/32, NE/32), 256>>>(Wo, wo_hi, wo_lo, NE, NE);
    wsplit_kernel<<<dim3(FF/32, NE/32), 256>>>(W1, w1_hi, w1_lo, NE, FF);
    wsplit_kernel<<<dim3(NE/32, FF/32), 256>>>(W2, w2_hi, w2_lo, FF, NE);

    // 1) h = ln1(x) -> bf16 hi/lo
    ln_kernel<<<BT, 256>>>(x, g1, be1, h_hi, h_lo);

    // 2) q,k,v = h @ W{q,k,v} -> bf16 hi/lo
    dim3 gQKV(NE/128, BT/128);
    mma_gemm<false,false,false,false,true><<<gQKV, 256, SMEMB>>>(
        h_hi, h_lo, wq_hi, wq_lo, nullptr, nullptr, nullptr, q_hi, q_lo, BT, NE, NE);
    mma_gemm<false,false,false,false,true><<<gQKV, 256, SMEMB>>>(
        h_hi, h_lo, wk_hi, wk_lo, nullptr, nullptr, nullptr, k_hi, k_lo, BT, NE, NE);
    mma_gemm<false,false,false,false,true><<<gQKV, 256, SMEMB>>>(
        h_hi, h_lo, wv_hi, wv_lo, nullptr, nullptr, nullptr, v_hi, v_lo, BT, NE, NE);

    // 3) tensor-core causal flash attention -> bf16 hi/lo
    dim3 gAtt(TT/128, BB*NH);
    attn_mma_kernel<<<gAtt, 256, ASMEM>>>(q_hi, q_lo, k_hi, k_lo, v_hi, v_lo,
                                          at_hi, at_lo);

    // 4) out = attn @ Wo + bo + x
    mma_gemm<true,false,true,true,false><<<gQKV, 256, SMEMB>>>(
        at_hi, at_lo, wo_hi, wo_lo, bo, x, out, nullptr, nullptr, BT, NE, NE);

    // 5) h = ln2(out)
    ln_kernel<<<BT, 256>>>(out, g2, be2, h_hi, h_lo);

    // 6) ff = relu(h @ W1 + b1) -> bf16 hi/lo
    dim3 gF1(FF/128, BT/128);
    mma_gemm<true,true,false,false,true><<<gF1, 256, SMEMB>>>(
        h_hi, h_lo, w1_hi, w1_lo, b1, nullptr, nullptr, ff_hi, ff_lo, BT, FF, NE);

    // 7) out = ff @ W2 + b2 + out
    dim3 gF2(NE/128, BT/128);
    mma_gemm<true,false,true,true,false><<<gF2, 256, SMEMB>>>(
        ff_hi, ff_lo, w2_hi, w2_lo, b2, out, out, nullptr, nullptr, BT, NE, FF);
}

// round 9
// speedup vs baseline: 11.1969x; 2.4151x over previous
#include <cuda_runtime.h>
#include <cuda_fp16.h>
#include <cstdint>
#include <math.h>

// Problem constants
#define NE    1024
#define NH    16
#define HS    64
#define TT    2048
#define BB    2
#define BT    (BB*TT)   // 4096
#define FF    4096
#define LN_EPS 1e-5f

// ---------------- scratch (device globals) ----------------
__device__ __half g_h[(size_t)BT*NE];
__device__ __half g_q[(size_t)BT*NE], g_k[(size_t)BT*NE], g_v[(size_t)BT*NE];
__device__ __half g_at[(size_t)BT*NE];
__device__ __half g_ff[(size_t)BT*FF];
// transposed weights: [N,K] K-major, fp16
__device__ __half g_wq[NE*NE], g_wk[NE*NE], g_wv[NE*NE], g_wo[NE*NE];
__device__ __half g_w1[(size_t)NE*FF], g_w2[(size_t)NE*FF];

// ---------------- PTX helpers ----------------
__device__ __forceinline__ uint32_t smem_u32(const void* p) {
    uint32_t a;
    asm("{ .reg .u64 t; cvta.to.shared.u64 t, %1; cvt.u32.u64 %0, t; }" : "=r"(a) : "l"(p));
    return a;
}

__device__ __forceinline__ void ldsm4(uint32_t* r, uint32_t addr) {
    asm volatile("ldmatrix.sync.aligned.m8n8.x4.shared.b16 {%0,%1,%2,%3}, [%4];"
        : "=r"(r[0]), "=r"(r[1]), "=r"(r[2]), "=r"(r[3]) : "r"(addr));
}

__device__ __forceinline__ void ldsm4t(uint32_t* r, uint32_t addr) {
    asm volatile("ldmatrix.sync.aligned.m8n8.x4.trans.shared.b16 {%0,%1,%2,%3}, [%4];"
        : "=r"(r[0]), "=r"(r[1]), "=r"(r[2]), "=r"(r[3]) : "r"(addr));
}

__device__ __forceinline__ void mma16816(float* c, const uint32_t* a, const uint32_t* b) {
    asm volatile("mma.sync.aligned.m16n8k16.row.col.f32.f16.f16.f32 "
        "{%0,%1,%2,%3}, {%4,%5,%6,%7}, {%8,%9}, {%0,%1,%2,%3};"
        : "+f"(c[0]), "+f"(c[1]), "+f"(c[2]), "+f"(c[3])
        : "r"(a[0]), "r"(a[1]), "r"(a[2]), "r"(a[3]), "r"(b[0]), "r"(b[1]));
}

__device__ __forceinline__ uint32_t packh(float a, float b) {
    __half2 t = __floats2half2_rn(a, b);
    return *(uint32_t*)&t;
}

// ---------------- weight transpose + fp16 convert ----------------
// W[K,N] fp32 -> T[N,K] fp16
__global__ __launch_bounds__(256) void wsplit_kernel(
    const float* __restrict__ W, __half* __restrict__ T, int K, int N)
{
    __shared__ float t[32][33];
    const int tx = threadIdx.x & 31, ty = threadIdx.x >> 5;
    const int nb = blockIdx.x * 32, kb = blockIdx.y * 32;
    #pragma unroll
    for (int i = 0; i < 4; i++) {
        const int k = kb + ty + i * 8;
        t[ty + i * 8][tx] = W[(size_t)k * N + nb + tx];
    }
    __syncthreads();
    #pragma unroll
    for (int i = 0; i < 4; i++) {
        const int n = nb + ty + i * 8;
        T[(size_t)n * K + kb + tx] = __float2half(t[tx][ty + i * 8]);
    }
}

// ---------------- LayerNorm -> fp16 ----------------
__global__ __launch_bounds__(256) void ln_kernel(
    const float* __restrict__ X, const float* __restrict__ G,
    const float* __restrict__ Be, __half* __restrict__ Y)
{
    const int row = blockIdx.x;
    const float* xr = X + (size_t)row * NE;
    const int tid = threadIdx.x;

    float4 xv = ((const float4*)xr)[tid];
    float s  = xv.x + xv.y + xv.z + xv.w;
    float ss = xv.x*xv.x + xv.y*xv.y + xv.z*xv.z + xv.w*xv.w;

    __shared__ float red_s[32], red_q[32];
    const int lane = tid & 31, wid = tid >> 5;
    #pragma unroll
    for (int o = 16; o > 0; o >>= 1) {
        s  += __shfl_xor_sync(0xffffffffu, s, o);
        ss += __shfl_xor_sync(0xffffffffu, ss, o);
    }
    if (lane == 0) { red_s[wid] = s; red_q[wid] = ss; }
    __syncthreads();
    if (wid == 0) {
        s  = (lane < 8) ? red_s[lane] : 0.f;
        ss = (lane < 8) ? red_q[lane] : 0.f;
        #pragma unroll
        for (int o = 4; o > 0; o >>= 1) {
            s  += __shfl_xor_sync(0xffffffffu, s, o);
            ss += __shfl_xor_sync(0xffffffffu, ss, o);
        }
        if (lane == 0) { red_s[0] = s; red_q[0] = ss; }
    }
    __syncthreads();
    const float mu   = red_s[0] * (1.0f / NE);
    const float var  = red_q[0] * (1.0f / NE) - mu * mu;
    const float rstd = rsqrtf(var + LN_EPS);

    float4 gv = ((const float4*)G)[tid];
    float4 bv = ((const float4*)Be)[tid];
    __half2* yp = (__half2*)(Y + (size_t)row * NE + tid * 4);
    yp[0] = __floats2half2_rn((xv.x - mu) * rstd * gv.x + bv.x,
                              (xv.y - mu) * rstd * gv.y + bv.y);
    yp[1] = __floats2half2_rn((xv.z - mu) * rstd * gv.z + bv.z,
                              (xv.w - mu) * rstd * gv.w + bv.w);
}

// ---------------- mma.sync fp16 GEMM ----------------
// C[M,N] = A[M,K] @ Bt[N,K]^T, fp32 accum, single-pass fp16.
// CTA tile 128x128xBK32, 8 warps (warp tile 64x32), 3-stage cp.async.
#define BK 32
#define STAGES 3
#define ROWB 80                  // padded smem row stride (bytes) for 32 fp16
#define MATB (128*ROWB)          // 10240 per matrix tile
#define STAGEB (2*MATB)          // A, B
#define SMEMB (STAGES*STAGEB)    // 61440 bytes

template<bool BIAS, bool RELU, bool RES, bool OUTF32, bool OUTH>
__global__ __launch_bounds__(256) void mma_gemm(
    const __half* __restrict__ A, const __half* __restrict__ B,
    const float* __restrict__ bias, const float* __restrict__ res,
    float* __restrict__ Cf, __half* __restrict__ Ch, int M, int N, int K)
{
    extern __shared__ char smem[];
    const uint32_t sb = smem_u32(smem);
    const int tid = threadIdx.x;
    const int warp = tid >> 5, lane = tid & 31;
    const int n0 = blockIdx.x * 128, m0 = blockIdx.y * 128;
    const int Ku4 = K >> 3;
    const int nch = K / BK;

    const uint4* srcs[2] = { (const uint4*)A, (const uint4*)B };

    // constant-in-flight-group invariant (empty commit at tail)
    auto issue = [&](int kc, int s) {
        if (kc < nch) {
            const uint32_t stage = sb + (uint32_t)s * STAGEB;
            #pragma unroll
            for (int q = 0; q < 4; q++) {
                const int idx = q * 256 + tid;
                const int mat = idx >> 9;
                const int wi  = idx & 511;
                const int row = wi >> 2, u = wi & 3;
                const int r0 = (mat == 0) ? m0 : n0;
                const uint4* g = srcs[mat] + (size_t)(r0 + row) * Ku4 + kc * 4 + u;
                const uint32_t sa = stage + mat * MATB + row * ROWB + u * 16;
                asm volatile("cp.async.cg.shared.global [%0], [%1], 16;"
                             :: "r"(sa), "l"(g));
            }
        }
        asm volatile("cp.async.commit_group;" ::: "memory");
    };

    float acc[4][4][4];
    #pragma unroll
    for (int i = 0; i < 4; i++)
        #pragma unroll
        for (int j = 0; j < 4; j++)
            #pragma unroll
            for (int r = 0; r < 4; r++) acc[i][j][r] = 0.f;

    const int wm = (warp >> 2) * 64;
    const int wn = (warp & 3) * 32;

    issue(0, 0);
    issue(1, 1);

    for (int kc = 0; kc < nch; kc++) {
        const int s = kc % STAGES;
        asm volatile("cp.async.wait_group 1;" ::: "memory");
        __syncthreads();
        issue(kc + 2, (kc + 2) % STAGES);

        const uint32_t stage = sb + (uint32_t)s * STAGEB;
        const uint32_t aBase = stage;
        const uint32_t bBase = stage + MATB;

        #pragma unroll
        for (int ks = 0; ks < 2; ks++) {
            uint32_t ah[4][4], bh[4][2];
            const int amat = lane >> 3;
            const int arr  = ((amat & 1) << 3) + (lane & 7);
            const int au   = ks * 2 + (amat >> 1);
            #pragma unroll
            for (int i = 0; i < 4; i++) {
                const uint32_t off = (uint32_t)((wm + i * 16 + arr) * ROWB + au * 16);
                ldsm4(ah[i], aBase + off);
            }
            const int bu   = ks * 2 + (amat & 1);
            const int brr  = ((amat >> 1) << 3) + (lane & 7);
            #pragma unroll
            for (int jp = 0; jp < 2; jp++) {
                const uint32_t off = (uint32_t)((wn + jp * 16 + brr) * ROWB + bu * 16);
                uint32_t t[4];
                ldsm4(t, bBase + off);
                bh[jp*2][0] = t[0]; bh[jp*2][1] = t[1];
                bh[jp*2+1][0] = t[2]; bh[jp*2+1][1] = t[3];
            }
            #pragma unroll
            for (int i = 0; i < 4; i++)
                #pragma unroll
                for (int j = 0; j < 4; j++) mma16816(acc[i][j], ah[i], bh[j]);
        }
        __syncthreads();
    }
    asm volatile("cp.async.wait_group 0;" ::: "memory");

    const int qrow = lane >> 2, qcol = (lane & 3) * 2;
    #pragma unroll
    for (int i = 0; i < 4; i++) {
        #pragma unroll
        for (int j = 0; j < 4; j++) {
            const int col = n0 + wn + j * 8 + qcol;
            float2 bv = make_float2(0.f, 0.f);
            if (BIAS) bv = *(const float2*)(bias + col);
            #pragma unroll
            for (int half_ = 0; half_ < 2; half_++) {
                const int row = m0 + wm + i * 16 + qrow + half_ * 8;
                float v0 = acc[i][j][half_ * 2 + 0];
                float v1 = acc[i][j][half_ * 2 + 1];
                if (BIAS) { v0 += bv.x; v1 += bv.y; }
                if (RELU) { v0 = fmaxf(v0, 0.f); v1 = fmaxf(v1, 0.f); }
                if (RES) {
                    float2 r = *(const float2*)(res + (size_t)row * N + col);
                    v0 += r.x; v1 += r.y;
                }
                if (OUTF32)
                    *(float2*)(Cf + (size_t)row * N + col) = make_float2(v0, v1);
                if (OUTH)
                    *(__half2*)(Ch + (size_t)row * N + col) = __floats2half2_rn(v0, v1);
            }
        }
    }
}

// ---------------- tensor-core causal flash attention (fp16) ----------------
// 256 threads (8 warps), one (b,h), 128-query tile, 64-key tiles,
// double-buffered cp.async, fp32 online softmax in accumulators.
#define AROWB 144
#define AQMAT (128*AROWB)               // 18432
#define AKMAT (64*AROWB)                // 9216
#define ASTAGE (2*AKMAT)                // K, V
#define ASMEM (AQMAT + 2*ASTAGE)        // 55296

__global__ __launch_bounds__(256) void attn_mma_kernel(
    const __half* __restrict__ Q, const __half* __restrict__ K,
    const __half* __restrict__ V, __half* __restrict__ O)
{
    extern __shared__ char smem[];
    const uint32_t sb = smem_u32(smem);
    const int tid = threadIdx.x, warp = tid >> 5, lane = tid & 31;
    const int bh = blockIdx.y, b = bh >> 4, h = bh & 15;
    const int qt = gridDim.x - 1 - blockIdx.x;     // heavy tiles first
    const int q0 = qt * 128;
    const size_t gbase = (size_t)b * TT * NE + h * HS;

    // Q tile: 128 rows x 8 chunks = 1024 chunks -> 4/thread
    {
        #pragma unroll
        for (int c = 0; c < 4; c++) {
            const int idx = c * 256 + tid;
            const int row = idx >> 3, u = idx & 7;
            const uint4* g = (const uint4*)(Q + gbase + (size_t)(q0 + row) * NE) + u;
            const uint32_t sa = sb + row * AROWB + u * 16;
            asm volatile("cp.async.cg.shared.global [%0], [%1], 16;" :: "r"(sa), "l"(g));
        }
        asm volatile("cp.async.commit_group;" ::: "memory");
    }

    const __half* kvsrc[2] = { K, V };
    auto issue_kv = [&](int t, int s) {
        if (t >= 0) {
            const int k0 = t * 64;
            const uint32_t stage = sb + AQMAT + (uint32_t)s * ASTAGE;
            #pragma unroll
            for (int c = 0; c < 4; c++) {
                const int idx = c * 256 + tid;
                const int mat = idx >> 9, wi = idx & 511;
                const int row = wi >> 3, u = wi & 7;
                const uint4* g = (const uint4*)(kvsrc[mat] + gbase + (size_t)(k0 + row) * NE) + u;
                const uint32_t sa = stage + mat * AKMAT + row * AROWB + u * 16;
                asm volatile("cp.async.cg.shared.global [%0], [%1], 16;" :: "r"(sa), "l"(g));
            }
        }
        asm volatile("cp.async.commit_group;" ::: "memory");
    };

    const int ntiles = 2 * (qt + 1);
    issue_kv(0, 0);

    float m[2] = { -1e30f, -1e30f }, l[2] = { 0.f, 0.f };
    float o[8][4];
    #pragma unroll
    for (int nt = 0; nt < 8; nt++)
        #pragma unroll
        for (int e = 0; e < 4; e++) o[nt][e] = 0.f;

    const float scale = 0.03125f;   // 1024^-0.5, faithful to source
    const int amat = lane >> 3;
    const int arr  = ((amat & 1) << 3) + (lane & 7);
    const int ahalf = amat >> 1;
    const int brr  = ((amat >> 1) << 3) + (lane & 7);
    const int bhalf = amat & 1;
    const int vrow  = ((amat & 1) << 3) + (lane & 7);
    const int vhalf = lane >> 4;

    for (int t = 0; t < ntiles; t++) {
        issue_kv((t + 1 < ntiles) ? t + 1 : -1, (t + 1) & 1);
        asm volatile("cp.async.wait_group 1;" ::: "memory");
        __syncthreads();

        const int k0 = t * 64;
        const uint32_t stage = sb + AQMAT + (uint32_t)(t & 1) * ASTAGE;
        const uint32_t kB = stage, vB = stage + AKMAT;

        // ----- S = Q K^T -----
        float s[8][4];
        #pragma unroll
        for (int nt = 0; nt < 8; nt++)
            #pragma unroll
            for (int e = 0; e < 4; e++) s[nt][e] = 0.f;

        #pragma unroll
        for (int kc = 0; kc < 4; kc++) {
            uint32_t af[4];
            ldsm4(af, sb + (uint32_t)((warp * 16 + arr) * AROWB + kc * 32 + ahalf * 16));
            #pragma unroll
            for (int jp = 0; jp < 4; jp++) {
                uint32_t tt[4];
                ldsm4(tt, kB + (uint32_t)((jp * 16 + brr) * AROWB + kc * 32 + bhalf * 16));
                uint32_t b0[2] = { tt[0], tt[1] }, b1[2] = { tt[2], tt[3] };
                mma16816(s[jp * 2],     af, b0);
                mma16816(s[jp * 2 + 1], af, b1);
            }
        }

        // ----- scale + causal mask + online softmax -----
        const bool domask = (k0 + 63 > q0);
        float mnew[2] = { m[0], m[1] };
        #pragma unroll
        for (int nt = 0; nt < 8; nt++)
            #pragma unroll
            for (int e = 0; e < 4; e++) {
                float v = s[nt][e] * scale;
                if (domask) {
                    const int key = k0 + nt * 8 + (lane & 3) * 2 + (e & 1);
                    const int qq  = q0 + warp * 16 + (lane >> 2) + (e >> 1) * 8;
                    if (key > qq) v = -1e30f;
                }
                s[nt][e] = v;
                mnew[e >> 1] = fmaxf(mnew[e >> 1], v);
            }
        #pragma unroll
        for (int r = 0; r < 2; r++) {
            mnew[r] = fmaxf(mnew[r], __shfl_xor_sync(0xffffffffu, mnew[r], 1));
            mnew[r] = fmaxf(mnew[r], __shfl_xor_sync(0xffffffffu, mnew[r], 2));
        }
        float corr[2], psum[2] = { 0.f, 0.f };
        corr[0] = __expf(m[0] - mnew[0]);
        corr[1] = __expf(m[1] - mnew[1]);
        m[0] = mnew[0]; m[1] = mnew[1];
        #pragma unroll
        for (int nt = 0; nt < 8; nt++)
            #pragma unroll
            for (int e = 0; e < 4; e++) {
                const float p_ = __expf(s[nt][e] - mnew[e >> 1]);
                s[nt][e] = p_;
                psum[e >> 1] += p_;
            }
        #pragma unroll
        for (int r = 0; r < 2; r++) {
            psum[r] += __shfl_xor_sync(0xffffffffu, psum[r], 1);
            psum[r] += __shfl_xor_sync(0xffffffffu, psum[r], 2);
            l[r] = l[r] * corr[r] + psum[r];
        }
        #pragma unroll
        for (int nt = 0; nt < 8; nt++)
            #pragma unroll
            for (int e = 0; e < 4; e++) o[nt][e] *= corr[e >> 1];

        // ----- O += P V -----
        #pragma unroll
        for (int kk = 0; kk < 4; kk++) {
            uint32_t ph[4];
            ph[0] = packh(s[2*kk][0],   s[2*kk][1]);
            ph[1] = packh(s[2*kk][2],   s[2*kk][3]);
            ph[2] = packh(s[2*kk+1][0], s[2*kk+1][1]);
            ph[3] = packh(s[2*kk+1][2], s[2*kk+1][3]);
            #pragma unroll
            for (int jp = 0; jp < 4; jp++) {
                const uint32_t va =
                    (uint32_t)((kk * 16 + vrow) * AROWB + jp * 32 + vhalf * 16);
                uint32_t th[4];
                ldsm4t(th, vB + va);
                uint32_t bh0[2] = { th[0], th[1] }, bh1[2] = { th[2], th[3] };
                mma16816(o[jp*2],   ph, bh0);
                mma16816(o[jp*2+1], ph, bh1);
            }
        }
        __syncthreads();
    }

    // ----- epilogue: O / l -> fp16 -----
    const float inv0 = 1.0f / l[0], inv1 = 1.0f / l[1];
    const int r0 = q0 + warp * 16 + (lane >> 2);
    const int r1 = r0 + 8;
    #pragma unroll
    for (int nt = 0; nt < 8; nt++) {
        const int col = nt * 8 + (lane & 3) * 2;
        *(__half2*)(O + gbase + (size_t)r0 * NE + col) =
            __floats2half2_rn(o[nt][0] * inv0, o[nt][1] * inv0);
        *(__half2*)(O + gbase + (size_t)r1 * NE + col) =
            __floats2half2_rn(o[nt][2] * inv1, o[nt][3] * inv1);
    }
}

// ---------------- launch ----------------
extern "C" void kernel_launch(void* const* d_in, const int* in_sizes, int n_in,
                              void* d_out, int out_size)
{
    const float* x  = (const float*)d_in[0];
    const float* Wq = (const float*)d_in[1];
    const float* Wk = (const float*)d_in[2];
    const float* Wv = (const float*)d_in[3];
    const float* Wo = (const float*)d_in[4];
    const float* bo = (const float*)d_in[5];
    const float* W1 = (const float*)d_in[6];
    const float* b1 = (const float*)d_in[7];
    const float* W2 = (const float*)d_in[8];
    const float* b2 = (const float*)d_in[9];
    const float* g1  = (const float*)d_in[10];
    const float* be1 = (const float*)d_in[11];
    const float* g2  = (const float*)d_in[12];
    const float* be2 = (const float*)d_in[13];
    float* out = (float*)d_out;

    __half *h, *q, *k, *v, *at, *ff, *wq, *wk, *wv, *wo, *w1, *w2;
    cudaGetSymbolAddress((void**)&h, g_h);
    cudaGetSymbolAddress((void**)&q, g_q);   cudaGetSymbolAddress((void**)&k, g_k);
    cudaGetSymbolAddress((void**)&v, g_v);   cudaGetSymbolAddress((void**)&at, g_at);
    cudaGetSymbolAddress((void**)&ff, g_ff);
    cudaGetSymbolAddress((void**)&wq, g_wq); cudaGetSymbolAddress((void**)&wk, g_wk);
    cudaGetSymbolAddress((void**)&wv, g_wv); cudaGetSymbolAddress((void**)&wo, g_wo);
    cudaGetSymbolAddress((void**)&w1, g_w1); cudaGetSymbolAddress((void**)&w2, g_w2);

    cudaFuncSetAttribute(mma_gemm<false,false,false,false,true>,
                         cudaFuncAttributeMaxDynamicSharedMemorySize, SMEMB);
    cudaFuncSetAttribute(mma_gemm<true,false,true,true,false>,
                         cudaFuncAttributeMaxDynamicSharedMemorySize, SMEMB);
    cudaFuncSetAttribute(mma_gemm<true,true,false,false,true>,
                         cudaFuncAttributeMaxDynamicSharedMemorySize, SMEMB);
    cudaFuncSetAttribute(attn_mma_kernel,
                         cudaFuncAttributeMaxDynamicSharedMemorySize, ASMEM);

    dim3 gQKV(NE/128, BT/128);
    dim3 gF1(FF/128, BT/128);
    dim3 gF2(NE/128, BT/128);

    // Launch order arranged so ncu's fixed skip (-s 5) profiles a GEMM (idx 5).
    wsplit_kernel<<<dim3(NE/32, NE/32), 256>>>(Wq, wq, NE, NE);            // 0
    wsplit_kernel<<<dim3(NE/32, NE/32), 256>>>(Wk, wk, NE, NE);            // 1
    wsplit_kernel<<<dim3(NE/32, NE/32), 256>>>(Wv, wv, NE, NE);            // 2
    ln_kernel<<<BT, 256>>>(x, g1, be1, h);                                 // 3
    mma_gemm<false,false,false,false,true><<<gQKV, 256, SMEMB>>>(
        h, wq, nullptr, nullptr, nullptr, q, BT, NE, NE);                  // 4
    mma_gemm<false,false,false,false,true><<<gQKV, 256, SMEMB>>>(
        h, wk, nullptr, nullptr, nullptr, k, BT, NE, NE);                  // 5 <- profiled
    mma_gemm<false,false,false,false,true><<<gQKV, 256, SMEMB>>>(
        h, wv, nullptr, nullptr, nullptr, v, BT, NE, NE);                  // 6
    wsplit_kernel<<<dim3(NE/32, NE/32), 256>>>(Wo, wo, NE, NE);            // 7
    dim3 gAtt(TT/128, BB*NH);
    attn_mma_kernel<<<gAtt, 256, ASMEM>>>(q, k, v, at);                    // 8
    mma_gemm<true,false,true,true,false><<<gQKV, 256, SMEMB>>>(
        at, wo, bo, x, out, nullptr, BT, NE, NE);                          // 9
    ln_kernel<<<BT, 256>>>(out, g2, be2, h);                               // 10
    wsplit_kernel<<<dim3(FF/32, NE/32), 256>>>(W1, w1, NE, FF);            // 11
    mma_gemm<true,true,false,false,true><<<gF1, 256, SMEMB>>>(
        h, w1, b1, nullptr, nullptr, ff, BT, FF, NE);                      // 12
    wsplit_kernel<<<dim3(NE/32, FF/32), 256>>>(W2, w2, FF, NE);            // 13
    mma_gemm<true,false,true,true,false><<<gF2, 256, SMEMB>>>(
        ff, w2, b2, out, out, nullptr, BT, NE, FF);                        // 14
}

// round 10
// speedup vs baseline: 11.6831x; 1.0434x over previous
#include <cuda_runtime.h>
#include <cuda_fp16.h>
#include <cstdint>
#include <math.h>

// Problem constants
#define NE    1024
#define NH    16
#define HS    64
#define TT    2048
#define BB    2
#define BT    (BB*TT)   // 4096
#define FF    4096
#define LN_EPS 1e-5f
#define SQ3   (3*NE)    // fused qkv row stride

// ---------------- scratch (device globals) ----------------
__device__ __half g_h[(size_t)BT*NE];
__device__ __half g_qkv[(size_t)BT*SQ3];
__device__ __half g_at[(size_t)BT*NE];
__device__ __half g_ff[(size_t)BT*FF];
// fp16 weights, SAME [K,N] layout as source (no transpose)
__device__ __half g_wqkv[(size_t)NE*SQ3];   // [1024][3072] = Wq|Wk|Wv
__device__ __half g_wo[(size_t)NE*NE];
__device__ __half g_w1[(size_t)NE*FF];
__device__ __half g_w2[(size_t)FF*NE];

// ---------------- PTX helpers ----------------
__device__ __forceinline__ uint32_t smem_u32(const void* p) {
    uint32_t a;
    asm("{ .reg .u64 t; cvta.to.shared.u64 t, %1; cvt.u32.u64 %0, t; }" : "=r"(a) : "l"(p));
    return a;
}

__device__ __forceinline__ void ldsm4(uint32_t* r, uint32_t addr) {
    asm volatile("ldmatrix.sync.aligned.m8n8.x4.shared.b16 {%0,%1,%2,%3}, [%4];"
        : "=r"(r[0]), "=r"(r[1]), "=r"(r[2]), "=r"(r[3]) : "r"(addr));
}

__device__ __forceinline__ void ldsm4t(uint32_t* r, uint32_t addr) {
    asm volatile("ldmatrix.sync.aligned.m8n8.x4.trans.shared.b16 {%0,%1,%2,%3}, [%4];"
        : "=r"(r[0]), "=r"(r[1]), "=r"(r[2]), "=r"(r[3]) : "r"(addr));
}

__device__ __forceinline__ void mma16816(float* c, const uint32_t* a, const uint32_t* b) {
    asm volatile("mma.sync.aligned.m16n8k16.row.col.f32.f16.f16.f32 "
        "{%0,%1,%2,%3}, {%4,%5,%6,%7}, {%8,%9}, {%0,%1,%2,%3};"
        : "+f"(c[0]), "+f"(c[1]), "+f"(c[2]), "+f"(c[3])
        : "r"(a[0]), "r"(a[1]), "r"(a[2]), "r"(a[3]), "r"(b[0]), "r"(b[1]));
}

__device__ __forceinline__ uint32_t packh(float a, float b) {
    __half2 t = __floats2half2_rn(a, b);
    return *(uint32_t*)&t;
}

// ---------------- weight fp32 -> fp16 streaming cast (layout-preserving) ----------------
// out[k][colOff + n] = (half)in[k][n];  in: [K][N], out row stride outN.
__global__ __launch_bounds__(256) void wconv_kernel(
    const float* __restrict__ W, __half* __restrict__ T,
    int N, int outN, int colOff, int total4)
{
    const int idx = blockIdx.x * 256 + threadIdx.x;
    if (idx >= total4) return;
    const int e = idx * 4;
    const int k = e / N, n = e - k * N;
    const float4 v = *(const float4*)(W + (size_t)k * N + n);
    __half* o = T + (size_t)k * outN + colOff + n;
    *(__half2*)o       = __floats2half2_rn(v.x, v.y);
    *(__half2*)(o + 2) = __floats2half2_rn(v.z, v.w);
}

// ---------------- LayerNorm -> fp16 ----------------
__global__ __launch_bounds__(256) void ln_kernel(
    const float* __restrict__ X, const float* __restrict__ G,
    const float* __restrict__ Be, __half* __restrict__ Y)
{
    const int row = blockIdx.x;
    const float* xr = X + (size_t)row * NE;
    const int tid = threadIdx.x;

    float4 xv = ((const float4*)xr)[tid];
    float s  = xv.x + xv.y + xv.z + xv.w;
    float ss = xv.x*xv.x + xv.y*xv.y + xv.z*xv.z + xv.w*xv.w;

    __shared__ float red_s[32], red_q[32];
    const int lane = tid & 31, wid = tid >> 5;
    #pragma unroll
    for (int o = 16; o > 0; o >>= 1) {
        s  += __shfl_xor_sync(0xffffffffu, s, o);
        ss += __shfl_xor_sync(0xffffffffu, ss, o);
    }
    if (lane == 0) { red_s[wid] = s; red_q[wid] = ss; }
    __syncthreads();
    if (wid == 0) {
        s  = (lane < 8) ? red_s[lane] : 0.f;
        ss = (lane < 8) ? red_q[lane] : 0.f;
        #pragma unroll
        for (int o = 4; o > 0; o >>= 1) {
            s  += __shfl_xor_sync(0xffffffffu, s, o);
            ss += __shfl_xor_sync(0xffffffffu, ss, o);
        }
        if (lane == 0) { red_s[0] = s; red_q[0] = ss; }
    }
    __syncthreads();
    const float mu   = red_s[0] * (1.0f / NE);
    const float var  = red_q[0] * (1.0f / NE) - mu * mu;
    const float rstd = rsqrtf(var + LN_EPS);

    float4 gv = ((const float4*)G)[tid];
    float4 bv = ((const float4*)Be)[tid];
    __half2* yp = (__half2*)(Y + (size_t)row * NE + tid * 4);
    yp[0] = __floats2half2_rn((xv.x - mu) * rstd * gv.x + bv.x,
                              (xv.y - mu) * rstd * gv.y + bv.y);
    yp[1] = __floats2half2_rn((xv.z - mu) * rstd * gv.z + bv.z,
                              (xv.w - mu) * rstd * gv.w + bv.w);
}

// ---------------- mma.sync fp16 GEMM, B in natural [K,N] layout ----------------
// C[M,N] = A[M,K] @ W[K,N], fp32 accum.
// CTA tile 128x128xBK32, 8 warps (64x32 warp tile), 3-stage cp.async.
// A smem: [m][k] rows (80B stride); B smem: [k][n] rows (272B stride),
// fragments via ldmatrix.trans (proven by the attention V path).
#define BK 32
#define STAGES 3
#define AROWBG 80
#define AMATBG (128*AROWBG)          // 10240
#define BROWBG 272                   // 128 fp16 = 256B data + 16B pad
#define BMATBG (32*BROWBG)           // 8704
#define STAGEB (AMATBG + BMATBG)     // 18944
#define SMEMB (STAGES*STAGEB)        // 56832

template<bool BIAS, bool RELU, bool RES, bool OUTF32, bool OUTH>
__global__ __launch_bounds__(256) void mma_gemm(
    const __half* __restrict__ A, const __half* __restrict__ B,
    const float* __restrict__ bias, const float* __restrict__ res,
    float* __restrict__ Cf, __half* __restrict__ Ch, int M, int N, int K)
{
    extern __shared__ char smem[];
    const uint32_t sb = smem_u32(smem);
    const int tid = threadIdx.x;
    const int warp = tid >> 5, lane = tid & 31;
    const int n0 = blockIdx.x * 128, m0 = blockIdx.y * 128;
    const int Ku4 = K >> 3, Nu4 = N >> 3;
    const int nch = K / BK;

    // constant-in-flight-group invariant (empty commit at tail)
    auto issue = [&](int kc, int s) {
        if (kc < nch) {
            const uint32_t stage = sb + (uint32_t)s * STAGEB;
            #pragma unroll
            for (int q = 0; q < 4; q++) {
                const int idx = q * 256 + tid;
                if (idx < 512) {            // A: 128 rows x 4 chunks
                    const int row = idx >> 2, u = idx & 3;
                    const uint4* g = (const uint4*)A + (size_t)(m0 + row) * Ku4 + kc * 4 + u;
                    const uint32_t sa = stage + row * AROWBG + u * 16;
                    asm volatile("cp.async.cg.shared.global [%0], [%1], 16;"
                                 :: "r"(sa), "l"(g));
                } else {                    // B: 32 k-rows x 16 chunks
                    const int wi = idx - 512;
                    const int row = wi >> 4, u = wi & 15;
                    const uint4* g = (const uint4*)B + (size_t)(kc * 32 + row) * Nu4 + (n0 >> 3) + u;
                    const uint32_t sa = stage + AMATBG + row * BROWBG + u * 16;
                    asm volatile("cp.async.cg.shared.global [%0], [%1], 16;"
                                 :: "r"(sa), "l"(g));
                }
            }
        }
        asm volatile("cp.async.commit_group;" ::: "memory");
    };

    float acc[4][4][4];
    #pragma unroll
    for (int i = 0; i < 4; i++)
        #pragma unroll
        for (int j = 0; j < 4; j++)
            #pragma unroll
            for (int r = 0; r < 4; r++) acc[i][j][r] = 0.f;

    const int wm = (warp >> 2) * 64;
    const int wn = (warp & 3) * 32;

    const int amat = lane >> 3;
    const int arr  = ((amat & 1) << 3) + (lane & 7);
    const int ahalf = amat >> 1;
    const int brow  = ((amat & 1) << 3) + (lane & 7);   // trans-unit row (k)
    const int bhsel = lane >> 4;                        // n-halfword select

    issue(0, 0);
    issue(1, 1);

    for (int kc = 0; kc < nch; kc++) {
        const int s = kc % STAGES;
        asm volatile("cp.async.wait_group 1;" ::: "memory");
        __syncthreads();
        issue(kc + 2, (kc + 2) % STAGES);

        const uint32_t stage = sb + (uint32_t)s * STAGEB;
        const uint32_t aBase = stage;
        const uint32_t bBase = stage + AMATBG;

        #pragma unroll
        for (int ks = 0; ks < 2; ks++) {
            uint32_t ah[4][4], bh[4][2];
            const int au = ks * 2 + (amat >> 1);
            #pragma unroll
            for (int i = 0; i < 4; i++) {
                const uint32_t off = (uint32_t)((wm + i * 16 + arr) * AROWBG + au * 16);
                ldsm4(ah[i], aBase + off);
            }
            // B fragments via ldmatrix.trans on [k][n] tile
            #pragma unroll
            for (int jp = 0; jp < 2; jp++) {
                const uint32_t off = (uint32_t)((ks * 16 + brow) * BROWBG
                                                + (wn + jp * 16) * 2 + bhsel * 16);
                uint32_t t[4];
                ldsm4t(t, bBase + off);
                bh[jp*2][0] = t[0]; bh[jp*2][1] = t[1];
                bh[jp*2+1][0] = t[2]; bh[jp*2+1][1] = t[3];
            }
            #pragma unroll
            for (int i = 0; i < 4; i++)
                #pragma unroll
                for (int j = 0; j < 4; j++) mma16816(acc[i][j], ah[i], bh[j]);
        }
        __syncthreads();
    }
    asm volatile("cp.async.wait_group 0;" ::: "memory");

    const int qrow = lane >> 2, qcol = (lane & 3) * 2;
    #pragma unroll
    for (int i = 0; i < 4; i++) {
        #pragma unroll
        for (int j = 0; j < 4; j++) {
            const int col = n0 + wn + j * 8 + qcol;
            float2 bv = make_float2(0.f, 0.f);
            if (BIAS) bv = *(const float2*)(bias + col);
            #pragma unroll
            for (int half_ = 0; half_ < 2; half_++) {
                const int row = m0 + wm + i * 16 + qrow + half_ * 8;
                float v0 = acc[i][j][half_ * 2 + 0];
                float v1 = acc[i][j][half_ * 2 + 1];
                if (BIAS) { v0 += bv.x; v1 += bv.y; }
                if (RELU) { v0 = fmaxf(v0, 0.f); v1 = fmaxf(v1, 0.f); }
                if (RES) {
                    float2 r = *(const float2*)(res + (size_t)row * N + col);
                    v0 += r.x; v1 += r.y;
                }
                if (OUTF32)
                    *(float2*)(Cf + (size_t)row * N + col) = make_float2(v0, v1);
                if (OUTH)
                    *(__half2*)(Ch + (size_t)row * N + col) = __floats2half2_rn(v0, v1);
            }
        }
    }
}

// ---------------- tensor-core causal flash attention (fp16, fused-qkv input) ----------------
#define AROWB 144
#define AQMAT (128*AROWB)               // 18432
#define AKMAT (64*AROWB)                // 9216
#define ASTAGE (2*AKMAT)                // K, V
#define ASMEM (AQMAT + 2*ASTAGE)        // 55296

__global__ __launch_bounds__(256) void attn_mma_kernel(
    const __half* __restrict__ QKV, __half* __restrict__ O)
{
    extern __shared__ char smem[];
    const uint32_t sb = smem_u32(smem);
    const int tid = threadIdx.x, warp = tid >> 5, lane = tid & 31;
    const int bh = blockIdx.y, b = bh >> 4, h = bh & 15;
    const int qt = gridDim.x - 1 - blockIdx.x;     // heavy tiles first
    const int q0 = qt * 128;
    const size_t qbase = (size_t)b * TT * SQ3 + h * HS;          // q cols
    const size_t obase = (size_t)b * TT * NE + h * HS;

    // Q tile: 128 rows x 8 chunks -> 4/thread
    {
        #pragma unroll
        for (int c = 0; c < 4; c++) {
            const int idx = c * 256 + tid;
            const int row = idx >> 3, u = idx & 7;
            const uint4* g = (const uint4*)(QKV + qbase + (size_t)(q0 + row) * SQ3) + u;
            const uint32_t sa = sb + row * AROWB + u * 16;
            asm volatile("cp.async.cg.shared.global [%0], [%1], 16;" :: "r"(sa), "l"(g));
        }
        asm volatile("cp.async.commit_group;" ::: "memory");
    }

    auto issue_kv = [&](int t, int s) {
        if (t >= 0) {
            const int k0 = t * 64;
            const uint32_t stage = sb + AQMAT + (uint32_t)s * ASTAGE;
            #pragma unroll
            for (int c = 0; c < 4; c++) {
                const int idx = c * 256 + tid;
                const int mat = idx >> 9, wi = idx & 511;
                const int row = wi >> 3, u = wi & 7;
                const uint4* g = (const uint4*)(QKV + qbase + (mat + 1) * NE
                                                + (size_t)(k0 + row) * SQ3) + u;
                const uint32_t sa = stage + mat * AKMAT + row * AROWB + u * 16;
                asm volatile("cp.async.cg.shared.global [%0], [%1], 16;" :: "r"(sa), "l"(g));
            }
        }
        asm volatile("cp.async.commit_group;" ::: "memory");
    };

    const int ntiles = 2 * (qt + 1);
    issue_kv(0, 0);

    float m[2] = { -1e30f, -1e30f }, l[2] = { 0.f, 0.f };
    float o[8][4];
    #pragma unroll
    for (int nt = 0; nt < 8; nt++)
        #pragma unroll
        for (int e = 0; e < 4; e++) o[nt][e] = 0.f;

    const float scale = 0.03125f;   // 1024^-0.5, faithful to source
    const int amat = lane >> 3;
    const int arr  = ((amat & 1) << 3) + (lane & 7);
    const int ahalf = amat >> 1;
    const int brr  = ((amat >> 1) << 3) + (lane & 7);
    const int bhalf = amat & 1;
    const int vrow  = ((amat & 1) << 3) + (lane & 7);
    const int vhalf = lane >> 4;

    for (int t = 0; t < ntiles; t++) {
        issue_kv((t + 1 < ntiles) ? t + 1 : -1, (t + 1) & 1);
        asm volatile("cp.async.wait_group 1;" ::: "memory");
        __syncthreads();

        const int k0 = t * 64;
        const uint32_t stage = sb + AQMAT + (uint32_t)(t & 1) * ASTAGE;
        const uint32_t kB = stage, vB = stage + AKMAT;

        // ----- S = Q K^T -----
        float s[8][4];
        #pragma unroll
        for (int nt = 0; nt < 8; nt++)
            #pragma unroll
            for (int e = 0; e < 4; e++) s[nt][e] = 0.f;

        #pragma unroll
        for (int kc = 0; kc < 4; kc++) {
            uint32_t af[4];
            ldsm4(af, sb + (uint32_t)((warp * 16 + arr) * AROWB + kc * 32 + ahalf * 16));
            #pragma unroll
            for (int jp = 0; jp < 4; jp++) {
                uint32_t tt[4];
                ldsm4(tt, kB + (uint32_t)((jp * 16 + brr) * AROWB + kc * 32 + bhalf * 16));
                uint32_t b0[2] = { tt[0], tt[1] }, b1[2] = { tt[2], tt[3] };
                mma16816(s[jp * 2],     af, b0);
                mma16816(s[jp * 2 + 1], af, b1);
            }
        }

        // ----- scale + causal mask + online softmax -----
        const bool domask = (k0 + 63 > q0);
        float mnew[2] = { m[0], m[1] };
        #pragma unroll
        for (int nt = 0; nt < 8; nt++)
            #pragma unroll
            for (int e = 0; e < 4; e++) {
                float v = s[nt][e] * scale;
                if (domask) {
                    const int key = k0 + nt * 8 + (lane & 3) * 2 + (e & 1);
                    const int qq  = q0 + warp * 16 + (lane >> 2) + (e >> 1) * 8;
                    if (key > qq) v = -1e30f;
                }
                s[nt][e] = v;
                mnew[e >> 1] = fmaxf(mnew[e >> 1], v);
            }
        #pragma unroll
        for (int r = 0; r < 2; r++) {
            mnew[r] = fmaxf(mnew[r], __shfl_xor_sync(0xffffffffu, mnew[r], 1));
            mnew[r] = fmaxf(mnew[r], __shfl_xor_sync(0xffffffffu, mnew[r], 2));
        }
        float corr[2], psum[2] = { 0.f, 0.f };
        corr[0] = __expf(m[0] - mnew[0]);
        corr[1] = __expf(m[1] - mnew[1]);
        m[0] = mnew[0]; m[1] = mnew[1];
        #pragma unroll
        for (int nt = 0; nt < 8; nt++)
            #pragma unroll
            for (int e = 0; e < 4; e++) {
                const float p_ = __expf(s[nt][e] - mnew[e >> 1]);
                s[nt][e] = p_;
                psum[e >> 1] += p_;
            }
        #pragma unroll
        for (int r = 0; r < 2; r++) {
            psum[r] += __shfl_xor_sync(0xffffffffu, psum[r], 1);
            psum[r] += __shfl_xor_sync(0xffffffffu, psum[r], 2);
            l[r] = l[r] * corr[r] + psum[r];
        }
        #pragma unroll
        for (int nt = 0; nt < 8; nt++)
            #pragma unroll
            for (int e = 0; e < 4; e++) o[nt][e] *= corr[e >> 1];

        // ----- O += P V -----
        #pragma unroll
        for (int kk = 0; kk < 4; kk++) {
            uint32_t ph[4];
            ph[0] = packh(s[2*kk][0],   s[2*kk][1]);
            ph[1] = packh(s[2*kk][2],   s[2*kk][3]);
            ph[2] = packh(s[2*kk+1][0], s[2*kk+1][1]);
            ph[3] = packh(s[2*kk+1][2], s[2*kk+1][3]);
            #pragma unroll
            for (int jp = 0; jp < 4; jp++) {
                const uint32_t va =
                    (uint32_t)((kk * 16 + vrow) * AROWB + jp * 32 + vhalf * 16);
                uint32_t th[4];
                ldsm4t(th, vB + va);
                uint32_t bh0[2] = { th[0], th[1] }, bh1[2] = { th[2], th[3] };
                mma16816(o[jp*2],   ph, bh0);
                mma16816(o[jp*2+1], ph, bh1);
            }
        }
        __syncthreads();
    }

    // ----- epilogue: O / l -> fp16 -----
    const float inv0 = 1.0f / l[0], inv1 = 1.0f / l[1];
    const int r0 = q0 + warp * 16 + (lane >> 2);
    const int r1 = r0 + 8;
    #pragma unroll
    for (int nt = 0; nt < 8; nt++) {
        const int col = nt * 8 + (lane & 3) * 2;
        *(__half2*)(O + obase + (size_t)r0 * NE + col) =
            __floats2half2_rn(o[nt][0] * inv0, o[nt][1] * inv0);
        *(__half2*)(O + obase + (size_t)r1 * NE + col) =
            __floats2half2_rn(o[nt][2] * inv1, o[nt][3] * inv1);
    }
}

// ---------------- launch ----------------
extern "C" void kernel_launch(void* const* d_in, const int* in_sizes, int n_in,
                              void* d_out, int out_size)
{
    const float* x  = (const float*)d_in[0];
    const float* Wq = (const float*)d_in[1];
    const float* Wk = (const float*)d_in[2];
    const float* Wv = (const float*)d_in[3];
    const float* Wo = (const float*)d_in[4];
    const float* bo = (const float*)d_in[5];
    const float* W1 = (const float*)d_in[6];
    const float* b1 = (const float*)d_in[7];
    const float* W2 = (const float*)d_in[8];
    const float* b2 = (const float*)d_in[9];
    const float* g1  = (const float*)d_in[10];
    const float* be1 = (const float*)d_in[11];
    const float* g2  = (const float*)d_in[12];
    const float* be2 = (const float*)d_in[13];
    float* out = (float*)d_out;

    __half *h, *qkv, *at, *ff, *wqkv, *wo, *w1, *w2;
    cudaGetSymbolAddress((void**)&h, g_h);
    cudaGetSymbolAddress((void**)&qkv, g_qkv);
    cudaGetSymbolAddress((void**)&at, g_at);
    cudaGetSymbolAddress((void**)&ff, g_ff);
    cudaGetSymbolAddress((void**)&wqkv, g_wqkv);
    cudaGetSymbolAddress((void**)&wo, g_wo);
    cudaGetSymbolAddress((void**)&w1, g_w1);
    cudaGetSymbolAddress((void**)&w2, g_w2);

    cudaFuncSetAttribute(mma_gemm<false,false,false,false,true>,
                         cudaFuncAttributeMaxDynamicSharedMemorySize, SMEMB);
    cudaFuncSetAttribute(mma_gemm<true,false,true,true,false>,
                         cudaFuncAttributeMaxDynamicSharedMemorySize, SMEMB);
    cudaFuncSetAttribute(mma_gemm<true,true,false,false,true>,
                         cudaFuncAttributeMaxDynamicSharedMemorySize, SMEMB);
    cudaFuncSetAttribute(attn_mma_kernel,
                         cudaFuncAttributeMaxDynamicSharedMemorySize, ASMEM);

    const int t4_ne  = NE * NE / 4;     // 262144 -> 1024 blocks
    const int t4_ff  = NE * FF / 4;     // 1048576 -> 4096 blocks

    // Launch order keeps ncu's fixed skip (-s 5) on the fused QKV GEMM.
    wconv_kernel<<<t4_ne/256, 256>>>(Wq, wqkv, NE, SQ3, 0,    t4_ne);      // 0
    wconv_kernel<<<t4_ne/256, 256>>>(Wk, wqkv, NE, SQ3, NE,   t4_ne);      // 1
    wconv_kernel<<<t4_ne/256, 256>>>(Wv, wqkv, NE, SQ3, 2*NE, t4_ne);      // 2
    ln_kernel<<<BT, 256>>>(x, g1, be1, h);                                 // 3
    wconv_kernel<<<t4_ne/256, 256>>>(Wo, wo, NE, NE, 0, t4_ne);            // 4
    dim3 gQKV(SQ3/128, BT/128);
    mma_gemm<false,false,false,false,true><<<gQKV, 256, SMEMB>>>(
        h, wqkv, nullptr, nullptr, nullptr, qkv, BT, SQ3, NE);             // 5 <- profiled
    dim3 gAtt(TT/128, BB*NH);
    attn_mma_kernel<<<gAtt, 256, ASMEM>>>(qkv, at);                        // 6
    dim3 gO(NE/128, BT/128);
    mma_gemm<true,false,true,true,false><<<gO, 256, SMEMB>>>(
        at, wo, bo, x, out, nullptr, BT, NE, NE);                          // 7
    ln_kernel<<<BT, 256>>>(out, g2, be2, h);                               // 8
    wconv_kernel<<<t4_ff/256, 256>>>(W1, w1, FF, FF, 0, t4_ff);            // 9
    dim3 gF1(FF/128, BT/128);
    mma_gemm<true,true,false,false,true><<<gF1, 256, SMEMB>>>(
        h, w1, b1, nullptr, nullptr, ff, BT, FF, NE);                      // 10
    wconv_kernel<<<t4_ff/256, 256>>>(W2, w2, NE, NE, 0, t4_ff);            // 11
    dim3 gF2(NE/128, BT/128);
    mma_gemm<true,false,true,true,false><<<gF2, 256, SMEMB>>>(
        ff, w2, b2, out, out, nullptr, BT, NE, FF);                        // 12
}